// round 8
// baseline (speedup 1.0000x reference)
#include <cuda_runtime.h>
#include <cuda_bf16.h>
#include <cuda_fp16.h>
#include <cstdint>
#include <math.h>

// Problem constants (fixed shapes)
#define T_TOK 8192
#define D_DIM 512
#define H_DIM 1024
#define E_NUM 8
#define K_TOP 2
#define PAIRS (T_TOK * K_TOP)   // 16384

// GEMM tile config
#define BM 128
#define BN 128
#define BK 64
#define NSTAGE 3
#define TILE_U16 (BM * BK)      // 8192 fp16 per tile (16KB)

// ---------------- device scratch (no allocations allowed) ----------------
__device__ uint16_t g_Xf[(size_t)T_TOK * D_DIM];             // x as fp16 bits
__device__ uint16_t g_Hf[(size_t)PAIRS * H_DIM];             // activations fp16
__device__ uint16_t g_W1f[(size_t)E_NUM * H_DIM * D_DIM];    // W1^T [E][H][D] fp16
__device__ uint16_t g_W2f[(size_t)E_NUM * D_DIM * H_DIM];    // W2^T [E][D][H] fp16
__device__ int   g_e0[T_TOK], g_e1[T_TOK];
__device__ float g_g0[T_TOK], g_g1[T_TOK];
__device__ int   g_cnt[E_NUM], g_off[E_NUM], g_cursor[E_NUM];
__device__ int   g_tok[PAIRS];
__device__ float g_gate[PAIRS];

// ---------------- helpers ----------------
__device__ __forceinline__ uint32_t smem_u32(const void* p) {
    uint32_t a;
    asm("{ .reg .u64 t; cvta.to.shared.u64 t, %1; cvt.u32.u64 %0, t; }" : "=r"(a) : "l"(p));
    return a;
}
__device__ __forceinline__ uint32_t packh2(float a, float b) {
    __half2 h = __floats2half2_rn(a, b);
    return *(uint32_t*)&h;
}

// mma.sync m16n8k16 fp16 (row.col), fp32 accum
__device__ __forceinline__ void mma16816(float* c, const uint32_t* a, const uint32_t* b) {
    asm volatile(
        "mma.sync.aligned.m16n8k16.row.col.f32.f16.f16.f32 "
        "{%0,%1,%2,%3}, {%4,%5,%6,%7}, {%8,%9}, {%0,%1,%2,%3};\n"
        : "+f"(c[0]), "+f"(c[1]), "+f"(c[2]), "+f"(c[3])
        : "r"(a[0]), "r"(a[1]), "r"(a[2]), "r"(a[3]), "r"(b[0]), "r"(b[1]));
}
__device__ __forceinline__ void ldsm4(uint32_t* r, uint32_t a) {
    asm volatile("ldmatrix.sync.aligned.m8n8.x4.shared.b16 {%0,%1,%2,%3}, [%4];"
        : "=r"(r[0]), "=r"(r[1]), "=r"(r[2]), "=r"(r[3]) : "r"(a));
}
__device__ __forceinline__ void cpa16(uint32_t dst, const void* src, int srcsz) {
    asm volatile("cp.async.cg.shared.global [%0], [%1], 16, %2;"
        :: "r"(dst), "l"(src), "r"(srcsz) : "memory");
}
#define CP_COMMIT() asm volatile("cp.async.commit_group;" ::: "memory")
#define CP_WAIT(n)  asm volatile("cp.async.wait_group %0;" :: "n"(n) : "memory")

// smem tile byte offset: 128B rows (64 fp16), seg = 16B segment (0..7), XOR swizzle
__device__ __forceinline__ uint32_t sw_off(int row, int seg) {
    return (uint32_t)(row * 128 + ((seg ^ (row & 7)) << 4));
}

// ---------------- 1) gating: logits, top-2, softmax; emits x fp16 ----------
__global__ void gate_kernel(const float* __restrict__ x,
                            const float* __restrict__ Wg) {
    __shared__ float xs[128][68];
    __shared__ float wgs[64][8];
    const int tid = threadIdx.x;
    const int t0  = blockIdx.x * 128;
    float acc[E_NUM];
#pragma unroll
    for (int e = 0; e < E_NUM; e++) acc[e] = 0.f;

    for (int k0 = 0; k0 < D_DIM; k0 += 64) {
#pragma unroll
        for (int i = 0; i < 4; i++) {
            int idx = tid + i * 128;
            wgs[idx >> 3][idx & 7] = Wg[(k0 + (idx >> 3)) * E_NUM + (idx & 7)];
        }
#pragma unroll
        for (int i = 0; i < 16; i++) {
            int f4  = i * 128 + tid;
            int row = f4 >> 4;
            int c4  = f4 & 15;
            float4 v = *(const float4*)(x + (size_t)(t0 + row) * D_DIM + k0 + c4 * 4);
            *(float4*)&xs[row][c4 * 4] = v;
            size_t o = (size_t)(t0 + row) * D_DIM + k0 + c4 * 4;
            *(uint2*)(g_Xf + o) = make_uint2(packh2(v.x, v.y), packh2(v.z, v.w));
        }
        __syncthreads();
#pragma unroll 8
        for (int k = 0; k < 64; k++) {
            float xv = xs[tid][k];
#pragma unroll
            for (int e = 0; e < E_NUM; e++) acc[e] = fmaf(xv, wgs[k][e], acc[e]);
        }
        __syncthreads();
    }
    int e0 = 0; float v0 = acc[0];
#pragma unroll
    for (int e = 1; e < E_NUM; e++) if (acc[e] > v0) { v0 = acc[e]; e0 = e; }
    int e1 = -1; float v1 = -INFINITY;
#pragma unroll
    for (int e = 0; e < E_NUM; e++) if (e != e0 && acc[e] > v1) { v1 = acc[e]; e1 = e; }
    float p1 = __expf(v1 - v0);
    float inv = 1.f / (1.f + p1);
    int t = t0 + tid;
    g_e0[t] = e0; g_e1[t] = e1;
    g_g0[t] = inv; g_g1[t] = p1 * inv;
}

// ---------------- 2) setup: reductions, offsets, losses ----------------
__global__ void setup_kernel(float* __restrict__ out) {
    __shared__ float simp[E_NUM][256];
    __shared__ int   scnt[E_NUM][256];
    const int tid = threadIdx.x;
    float imp[E_NUM]; int cnt[E_NUM];
#pragma unroll
    for (int e = 0; e < E_NUM; e++) { imp[e] = 0.f; cnt[e] = 0; }
    for (int t = tid; t < T_TOK; t += 256) {
        int a = g_e0[t]; imp[a] += g_g0[t]; cnt[a]++;
        int b = g_e1[t]; imp[b] += g_g1[t]; cnt[b]++;
    }
#pragma unroll
    for (int e = 0; e < E_NUM; e++) { simp[e][tid] = imp[e]; scnt[e][tid] = cnt[e]; }
    __syncthreads();
    for (int s = 128; s > 0; s >>= 1) {
        if (tid < s) {
#pragma unroll
            for (int e = 0; e < E_NUM; e++) {
                simp[e][tid] += simp[e][tid + s];
                scnt[e][tid] += scnt[e][tid + s];
            }
        }
        __syncthreads();
    }
    if (tid == 0) {
        const float eps = 1e-10f;
        int off = 0;
        float mi = 0.f, ml = 0.f;
#pragma unroll
        for (int e = 0; e < E_NUM; e++) {
            g_off[e] = off; g_cnt[e] = scnt[e][0]; g_cursor[e] = 0;
            off += scnt[e][0];
            mi += simp[e][0];
            ml += (float)scnt[e][0];
        }
        mi /= E_NUM; ml /= E_NUM;
        float vi = 0.f, vl = 0.f;
#pragma unroll
        for (int e = 0; e < E_NUM; e++) {
            float di = simp[e][0] - mi; vi += di * di;
            float dl = (float)scnt[e][0] - ml; vl += dl * dl;
        }
        vi /= (E_NUM - 1); vl /= (E_NUM - 1);
        out[(size_t)T_TOK * D_DIM]     = vi / (mi * mi + eps);
        out[(size_t)T_TOK * D_DIM + 1] = vl / (ml * ml + eps);
    }
}

// ---------------- 3) scatter ----------------
__global__ void scatter_kernel() {
    int t = blockIdx.x * 256 + threadIdx.x;
    if (t >= T_TOK) return;
    {
        int e = g_e0[t];
        int p = atomicAdd(&g_cursor[e], 1);
        int s = g_off[e] + p;
        g_tok[s] = t; g_gate[s] = g_g0[t];
    }
    {
        int e = g_e1[t];
        int p = atomicAdd(&g_cursor[e], 1);
        int s = g_off[e] + p;
        g_tok[s] = t; g_gate[s] = g_g1[t];
    }
}

// ------------- weight transpose + fp16 convert (128B store transactions) ----
// src s: [R rows][C cols] fp32; dst d: [C rows][R cols] fp16
template <int R, int C>
__device__ __forceinline__ void transpose_half(const float* __restrict__ s,
                                               uint16_t* __restrict__ d) {
    __shared__ float tile[64][33];
    const int r0 = blockIdx.y * 64, c0 = blockIdx.x * 32;
    const int tx = threadIdx.x, ty = threadIdx.y;  // (32, 8)
#pragma unroll
    for (int i = 0; i < 8; i++)
        tile[ty + i * 8][tx] = s[(size_t)(r0 + ty + i * 8) * C + c0 + tx];
    __syncthreads();
#pragma unroll
    for (int i = 0; i < 4; i++) {
        int c = ty + i * 8;                       // 0..31
        float v0 = tile[2 * tx][c], v1 = tile[2 * tx + 1][c];
        *(uint32_t*)(d + (size_t)(c0 + c) * R + r0 + 2 * tx) = packh2(v0, v1);
    }
}
__global__ void conv_w1_kernel(const float* __restrict__ W1) {
    int e = blockIdx.z;
    size_t eo = (size_t)e * D_DIM * H_DIM;
    transpose_half<D_DIM, H_DIM>(W1 + eo, g_W1f + eo);
}
__global__ void conv_w2_kernel(const float* __restrict__ W2) {
    int e = blockIdx.z;
    size_t eo = (size_t)e * H_DIM * D_DIM;
    transpose_half<H_DIM, D_DIM>(W2 + eo, g_W2f + eo);
}

// ---------------- shared GEMM smem ----------------
struct GS {
    uint16_t A[NSTAGE][TILE_U16];
    uint16_t B[NSTAGE][TILE_U16];
    int   toks[BM];
    float gates[BM];
    float bias[BN];
};
#define GS_BYTES sizeof(GS)

// compute one k64 chunk from stage st
__device__ __forceinline__ void compute_chunk(GS* gs, int st, int wm, int wn, int lid,
                                              float acc[4][4][4]) {
    const int r_ = lid & 7, mat = lid >> 3;
    uint32_t pA = smem_u32(gs->A[st]);
    uint32_t pB = smem_u32(gs->B[st]);
#pragma unroll
    for (int s = 0; s < 4; s++) {               // 4 k16 steps
        uint32_t bf[4][2];
#pragma unroll
        for (int np = 0; np < 2; np++) {
            int row = wn * 32 + np * 16 + ((mat >> 1) << 3) + r_;
            int seg = (s << 1) | (mat & 1);
            uint32_t t[4];
            ldsm4(t, pB + sw_off(row, seg));
            bf[np * 2][0]     = t[0]; bf[np * 2][1]     = t[1];
            bf[np * 2 + 1][0] = t[2]; bf[np * 2 + 1][1] = t[3];
        }
#pragma unroll
        for (int mi = 0; mi < 4; mi++) {
            int row = wm * 64 + mi * 16 + ((mat & 1) << 3) + r_;
            int seg = (s << 1) | (mat >> 1);
            uint32_t af[4];
            ldsm4(af, pA + sw_off(row, seg));
#pragma unroll
            for (int ni = 0; ni < 4; ni++)
                mma16816(acc[mi][ni], af, bf[ni]);
        }
    }
}

// fill one stage: A gathered by tok list, B linear
__device__ __forceinline__ void fill_stage(GS* gs, int st, int tid,
                                           const uint16_t* __restrict__ A,
                                           const uint16_t* __restrict__ B,
                                           int k0, int lda, int ldb, bool gatherA, int mrem) {
    uint32_t pA = smem_u32(gs->A[st]);
    uint32_t pB = smem_u32(gs->B[st]);
#pragma unroll
    for (int i = 0; i < 4; i++) {
        int id  = tid + i * 256;   // 0..1023
        int row = id >> 3, seg = id & 7;
        uint32_t d = sw_off(row, seg);
        int vs; size_t grow;
        if (gatherA) {
            int tok = gs->toks[row];
            vs = (tok >= 0) ? 16 : 0;
            grow = (tok >= 0) ? (size_t)tok : 0;
        } else {
            vs = (row < mrem) ? 16 : 0;
            grow = (row < mrem) ? (size_t)row : 0;
        }
        cpa16(pA + d, A + grow * lda + k0 + seg * 8, vs);
        cpa16(pB + d, B + (size_t)row * ldb + k0 + seg * 8, 16);
    }
}

// 3-stage mainloop: chunk c computes stage c%3 while prefetching chunk c+2
#define GEMM_MAINLOOP(NC, Ap, Bp, lda, ldb, gatherA)                              \
    fill_stage(gs, 0, tid, Ap, Bp, 0, lda, ldb, gatherA, mrem); CP_COMMIT();      \
    fill_stage(gs, 1, tid, Ap, Bp, BK, lda, ldb, gatherA, mrem); CP_COMMIT();     \
    {                                                                             \
        int st = 0;                                                               \
        for (int c = 0; c < (NC); c++) {                                          \
            CP_WAIT(1);                                                           \
            __syncthreads();                                                      \
            if (c + 2 < (NC))                                                     \
                fill_stage(gs, (st + 2) % NSTAGE, tid, Ap, Bp, (c + 2) * BK,      \
                           lda, ldb, gatherA, mrem);                              \
            CP_COMMIT();                                                          \
            compute_chunk(gs, st, wm, wn, lid, acc);                              \
            st = (st + 1) % NSTAGE;                                               \
        }                                                                         \
    }

// ---------------- 4) GEMM1: H = relu(gather(x) @ W1 + b1) ----------------
__global__ __launch_bounds__(256, 2)
void gemm1_mma(const float* __restrict__ b1) {
    extern __shared__ __align__(16) char smraw[];
    GS* gs = (GS*)smraw;
    const int e   = blockIdx.z;
    const int cnt = g_cnt[e];
    const int m0  = blockIdx.x * BM;
    if (m0 >= cnt) return;
    const int n0   = blockIdx.y * BN;
    const int off  = g_off[e];
    const int mrem = cnt - m0;
    const int tid  = threadIdx.x;
    const int wid  = tid >> 5, lid = tid & 31;
    const int wm = wid >> 2, wn = wid & 3;
    const int g = lid >> 2, q = lid & 3;

    if (tid < BM) {
        gs->toks[tid] = (tid < mrem) ? g_tok[off + m0 + tid] : -1;
        gs->bias[tid] = b1[(size_t)e * H_DIM + n0 + tid];
    }
    __syncthreads();

    float acc[4][4][4];
#pragma unroll
    for (int a = 0; a < 4; a++)
#pragma unroll
        for (int b = 0; b < 4; b++)
#pragma unroll
            for (int c = 0; c < 4; c++) acc[a][b][c] = 0.f;

    const uint16_t* Bp = g_W1f + ((size_t)e * H_DIM + n0) * D_DIM;

    GEMM_MAINLOOP(D_DIM / BK, g_Xf, Bp, D_DIM, D_DIM, true);

    // epilogue: bias + relu -> fp16 H
#pragma unroll
    for (int mi = 0; mi < 4; mi++) {
#pragma unroll
        for (int h = 0; h < 2; h++) {
            int mrow = wm * 64 + mi * 16 + g + h * 8;
            if (mrow < mrem) {
                size_t rb = (size_t)(off + m0 + mrow) * H_DIM + n0;
#pragma unroll
                for (int ni = 0; ni < 4; ni++) {
                    int n = wn * 32 + ni * 8 + q * 2;
                    float v0 = fmaxf(acc[mi][ni][h * 2 + 0] + gs->bias[n], 0.f);
                    float v1 = fmaxf(acc[mi][ni][h * 2 + 1] + gs->bias[n + 1], 0.f);
                    *(uint32_t*)(g_Hf + rb + n) = packh2(v0, v1);
                }
            }
        }
    }
}

// ---------------- 5) GEMM2: out += gate * (H @ W2 + b2) ----------------
__global__ __launch_bounds__(256, 2)
void gemm2_mma(const float* __restrict__ b2, float* __restrict__ out) {
    extern __shared__ __align__(16) char smraw[];
    GS* gs = (GS*)smraw;
    const int e   = blockIdx.z;
    const int cnt = g_cnt[e];
    const int m0  = blockIdx.x * BM;
    if (m0 >= cnt) return;
    const int n0   = blockIdx.y * BN;
    const int off  = g_off[e];
    const int mrem = cnt - m0;
    const int tid  = threadIdx.x;
    const int wid  = tid >> 5, lid = tid & 31;
    const int wm = wid >> 2, wn = wid & 3;
    const int g = lid >> 2, q = lid & 3;

    if (tid < BM) {
        int valid = tid < mrem;
        int s = off + m0 + tid;
        gs->toks[tid]  = valid ? g_tok[s] : -1;
        gs->gates[tid] = valid ? g_gate[s] : 0.f;
        gs->bias[tid]  = b2[(size_t)e * D_DIM + n0 + tid];
    }
    __syncthreads();

    float acc[4][4][4];
#pragma unroll
    for (int a = 0; a < 4; a++)
#pragma unroll
        for (int b = 0; b < 4; b++)
#pragma unroll
            for (int c = 0; c < 4; c++) acc[a][b][c] = 0.f;

    const uint16_t* Ap = g_Hf + (size_t)(off + m0) * H_DIM;
    const uint16_t* Bp = g_W2f + ((size_t)e * D_DIM + n0) * H_DIM;

    GEMM_MAINLOOP(H_DIM / BK, Ap, Bp, H_DIM, H_DIM, false);

    // epilogue: (acc + bias) * gate -> atomicAdd combine
#pragma unroll
    for (int mi = 0; mi < 4; mi++) {
#pragma unroll
        for (int h = 0; h < 2; h++) {
            int mrow = wm * 64 + mi * 16 + g + h * 8;
            if (mrow < mrem) {
                int tok  = gs->toks[mrow];
                float gt = gs->gates[mrow];
                float* dst = out + (size_t)tok * D_DIM + n0;
#pragma unroll
                for (int ni = 0; ni < 4; ni++) {
                    int n = wn * 32 + ni * 8 + q * 2;
                    atomicAdd(&dst[n],     (acc[mi][ni][h * 2 + 0] + gs->bias[n]) * gt);
                    atomicAdd(&dst[n + 1], (acc[mi][ni][h * 2 + 1] + gs->bias[n + 1]) * gt);
                }
            }
        }
    }
}

// ---------------- launch ----------------
extern "C" void kernel_launch(void* const* d_in, const int* in_sizes, int n_in,
                              void* d_out, int out_size) {
    const float* x  = (const float*)d_in[0];
    const float* Wg = (const float*)d_in[1];
    const float* W1 = (const float*)d_in[2];
    const float* b1 = (const float*)d_in[3];
    const float* W2 = (const float*)d_in[4];
    const float* b2 = (const float*)d_in[5];
    float* out = (float*)d_out;

    static bool attr_done = false;
    if (!attr_done) {
        cudaFuncSetAttribute(gemm1_mma, cudaFuncAttributeMaxDynamicSharedMemorySize, (int)GS_BYTES);
        cudaFuncSetAttribute(gemm2_mma, cudaFuncAttributeMaxDynamicSharedMemorySize, (int)GS_BYTES);
        attr_done = true;
    }

    cudaMemsetAsync(out, 0, (size_t)T_TOK * D_DIM * sizeof(float));

    gate_kernel<<<T_TOK / 128, 128>>>(x, Wg);
    setup_kernel<<<1, 256>>>(out);
    scatter_kernel<<<(T_TOK + 255) / 256, 256>>>();

    conv_w1_kernel<<<dim3(H_DIM / 32, D_DIM / 64, E_NUM), dim3(32, 8)>>>(W1);
    conv_w2_kernel<<<dim3(D_DIM / 32, H_DIM / 64, E_NUM), dim3(32, 8)>>>(W2);

    dim3 g1(T_TOK / BM, H_DIM / BN, E_NUM);   // (64, 8, 8), empty tiles exit
    gemm1_mma<<<g1, 256, GS_BYTES>>>(b1);

    dim3 g2(T_TOK / BM, D_DIM / BN, E_NUM);   // (64, 4, 8)
    gemm2_mma<<<g2, 256, GS_BYTES>>>(b2, out);
}

// round 10
// speedup vs baseline: 1.4296x; 1.4296x over previous
#include <cuda_runtime.h>
#include <cuda_bf16.h>
#include <cuda_fp16.h>
#include <cstdint>
#include <math.h>

// Problem constants (fixed shapes)
#define T_TOK 8192
#define D_DIM 512
#define H_DIM 1024
#define E_NUM 8
#define K_TOP 2
#define PAIRS (T_TOK * K_TOP)   // 16384

// GEMM tile config
#define BM 128
#define BN 128
#define BK 64
#define TILE_U16 (BM * BK)      // 8192 fp16 per tile (16KB)

// ---------------- device scratch (no allocations allowed) ----------------
__device__ uint16_t g_Xf[(size_t)T_TOK * D_DIM];             // x as fp16 bits
__device__ uint16_t g_Hf[(size_t)PAIRS * H_DIM];             // activations fp16
__device__ uint16_t g_W1f[(size_t)E_NUM * H_DIM * D_DIM];    // W1^T [E][H][D] fp16
__device__ uint16_t g_W2f[(size_t)E_NUM * D_DIM * H_DIM];    // W2^T [E][D][H] fp16
__device__ int   g_e0[T_TOK], g_e1[T_TOK];
__device__ float g_g0[T_TOK], g_g1[T_TOK];
__device__ int   g_cnt[E_NUM], g_off[E_NUM], g_cursor[E_NUM];
__device__ int   g_tok[PAIRS];
__device__ float g_gate[PAIRS];

// ---------------- helpers ----------------
__device__ __forceinline__ uint32_t smem_u32(const void* p) {
    uint32_t a;
    asm("{ .reg .u64 t; cvta.to.shared.u64 t, %1; cvt.u32.u64 %0, t; }" : "=r"(a) : "l"(p));
    return a;
}
__device__ __forceinline__ uint32_t packh2(float a, float b) {
    __half2 h = __floats2half2_rn(a, b);
    return *(uint32_t*)&h;
}

// mma.sync m16n8k16 fp16 (row.col), fp32 accum
__device__ __forceinline__ void mma16816(float* c, const uint32_t* a, const uint32_t* b) {
    asm volatile(
        "mma.sync.aligned.m16n8k16.row.col.f32.f16.f16.f32 "
        "{%0,%1,%2,%3}, {%4,%5,%6,%7}, {%8,%9}, {%0,%1,%2,%3};\n"
        : "+f"(c[0]), "+f"(c[1]), "+f"(c[2]), "+f"(c[3])
        : "r"(a[0]), "r"(a[1]), "r"(a[2]), "r"(a[3]), "r"(b[0]), "r"(b[1]));
}
__device__ __forceinline__ void ldsm4(uint32_t* r, uint32_t a) {
    asm volatile("ldmatrix.sync.aligned.m8n8.x4.shared.b16 {%0,%1,%2,%3}, [%4];"
        : "=r"(r[0]), "=r"(r[1]), "=r"(r[2]), "=r"(r[3]) : "r"(a));
}
__device__ __forceinline__ void cpa16(uint32_t dst, const void* src, int srcsz) {
    asm volatile("cp.async.cg.shared.global [%0], [%1], 16, %2;"
        :: "r"(dst), "l"(src), "r"(srcsz) : "memory");
}
#define CP_COMMIT() asm volatile("cp.async.commit_group;" ::: "memory")
#define CP_WAIT(n)  asm volatile("cp.async.wait_group %0;" :: "n"(n) : "memory")

// smem tile byte offset: 128B rows (64 fp16), seg = 16B segment (0..7), XOR swizzle
__device__ __forceinline__ uint32_t sw_off(int row, int seg) {
    return (uint32_t)(row * 128 + ((seg ^ (row & 7)) << 4));
}

// ---------------- 1) gating: logits, top-2, softmax; emits x fp16 ----------
__global__ void gate_kernel(const float* __restrict__ x,
                            const float* __restrict__ Wg) {
    __shared__ float xs[128][68];
    __shared__ float wgs[64][8];
    const int tid = threadIdx.x;
    const int t0  = blockIdx.x * 128;
    float acc[E_NUM];
#pragma unroll
    for (int e = 0; e < E_NUM; e++) acc[e] = 0.f;

    for (int k0 = 0; k0 < D_DIM; k0 += 64) {
#pragma unroll
        for (int i = 0; i < 4; i++) {
            int idx = tid + i * 128;
            wgs[idx >> 3][idx & 7] = Wg[(k0 + (idx >> 3)) * E_NUM + (idx & 7)];
        }
#pragma unroll
        for (int i = 0; i < 16; i++) {
            int f4  = i * 128 + tid;
            int row = f4 >> 4;
            int c4  = f4 & 15;
            float4 v = *(const float4*)(x + (size_t)(t0 + row) * D_DIM + k0 + c4 * 4);
            *(float4*)&xs[row][c4 * 4] = v;
            size_t o = (size_t)(t0 + row) * D_DIM + k0 + c4 * 4;
            *(uint2*)(g_Xf + o) = make_uint2(packh2(v.x, v.y), packh2(v.z, v.w));
        }
        __syncthreads();
#pragma unroll 8
        for (int k = 0; k < 64; k++) {
            float xv = xs[tid][k];
#pragma unroll
            for (int e = 0; e < E_NUM; e++) acc[e] = fmaf(xv, wgs[k][e], acc[e]);
        }
        __syncthreads();
    }
    int e0 = 0; float v0 = acc[0];
#pragma unroll
    for (int e = 1; e < E_NUM; e++) if (acc[e] > v0) { v0 = acc[e]; e0 = e; }
    int e1 = -1; float v1 = -INFINITY;
#pragma unroll
    for (int e = 0; e < E_NUM; e++) if (e != e0 && acc[e] > v1) { v1 = acc[e]; e1 = e; }
    float p1 = __expf(v1 - v0);
    float inv = 1.f / (1.f + p1);
    int t = t0 + tid;
    g_e0[t] = e0; g_e1[t] = e1;
    g_g0[t] = inv; g_g1[t] = p1 * inv;
}

// ---------------- 2) setup: reductions, offsets, losses ----------------
__global__ void setup_kernel(float* __restrict__ out) {
    __shared__ float simp[E_NUM][256];
    __shared__ int   scnt[E_NUM][256];
    const int tid = threadIdx.x;
    float imp[E_NUM]; int cnt[E_NUM];
#pragma unroll
    for (int e = 0; e < E_NUM; e++) { imp[e] = 0.f; cnt[e] = 0; }
    for (int t = tid; t < T_TOK; t += 256) {
        int a = g_e0[t]; imp[a] += g_g0[t]; cnt[a]++;
        int b = g_e1[t]; imp[b] += g_g1[t]; cnt[b]++;
    }
#pragma unroll
    for (int e = 0; e < E_NUM; e++) { simp[e][tid] = imp[e]; scnt[e][tid] = cnt[e]; }
    __syncthreads();
    for (int s = 128; s > 0; s >>= 1) {
        if (tid < s) {
#pragma unroll
            for (int e = 0; e < E_NUM; e++) {
                simp[e][tid] += simp[e][tid + s];
                scnt[e][tid] += scnt[e][tid + s];
            }
        }
        __syncthreads();
    }
    if (tid == 0) {
        const float eps = 1e-10f;
        int off = 0;
        float mi = 0.f, ml = 0.f;
#pragma unroll
        for (int e = 0; e < E_NUM; e++) {
            g_off[e] = off; g_cnt[e] = scnt[e][0]; g_cursor[e] = 0;
            off += scnt[e][0];
            mi += simp[e][0];
            ml += (float)scnt[e][0];
        }
        mi /= E_NUM; ml /= E_NUM;
        float vi = 0.f, vl = 0.f;
#pragma unroll
        for (int e = 0; e < E_NUM; e++) {
            float di = simp[e][0] - mi; vi += di * di;
            float dl = (float)scnt[e][0] - ml; vl += dl * dl;
        }
        vi /= (E_NUM - 1); vl /= (E_NUM - 1);
        out[(size_t)T_TOK * D_DIM]     = vi / (mi * mi + eps);
        out[(size_t)T_TOK * D_DIM + 1] = vl / (ml * ml + eps);
    }
}

// ---------------- 3) scatter ----------------
__global__ void scatter_kernel() {
    int t = blockIdx.x * 256 + threadIdx.x;
    if (t >= T_TOK) return;
    {
        int e = g_e0[t];
        int p = atomicAdd(&g_cursor[e], 1);
        int s = g_off[e] + p;
        g_tok[s] = t; g_gate[s] = g_g0[t];
    }
    {
        int e = g_e1[t];
        int p = atomicAdd(&g_cursor[e], 1);
        int s = g_off[e] + p;
        g_tok[s] = t; g_gate[s] = g_g1[t];
    }
}

// ------------- weight transpose + fp16 convert (fused W1+W2) -------------
// src s: [R rows][C cols] fp32; dst d: [C rows][R cols] fp16
template <int R, int C>
__device__ __forceinline__ void transpose_half(const float* __restrict__ s,
                                               uint16_t* __restrict__ d) {
    __shared__ float tile[32][33];
    int c0 = blockIdx.x * 32, r0 = blockIdx.y * 32;
#pragma unroll
    for (int i = 0; i < 32; i += 8)
        tile[threadIdx.y + i][threadIdx.x] = s[(size_t)(r0 + threadIdx.y + i) * C + c0 + threadIdx.x];
    __syncthreads();
#pragma unroll
    for (int i = 0; i < 32; i += 8) {
        float v = tile[threadIdx.x][threadIdx.y + i];
        __half h = __float2half_rn(v);
        d[(size_t)(c0 + threadIdx.y + i) * R + r0 + threadIdx.x] = *(uint16_t*)&h;
    }
}
// grid: (32, 32, 2*E) — max of both branch tile grids; each branch guards its bounds.
// z < E: W1 expert z (R=D=512 rows -> y<16, C=H=1024 cols -> x<32)
// z >= E: W2 expert z-E (R=H=1024 rows -> y<32, C=D=512 cols -> x<16)
__global__ void conv_w_kernel(const float* __restrict__ W1,
                              const float* __restrict__ W2) {
    int z = blockIdx.z;
    if (z < E_NUM) {
        if (blockIdx.x >= H_DIM / 32 || blockIdx.y >= D_DIM / 32) return;
        size_t eo = (size_t)z * D_DIM * H_DIM;
        transpose_half<D_DIM, H_DIM>(W1 + eo, g_W1f + eo);
    } else {
        if (blockIdx.x >= D_DIM / 32 || blockIdx.y >= H_DIM / 32) return;
        size_t eo = (size_t)(z - E_NUM) * H_DIM * D_DIM;
        transpose_half<H_DIM, D_DIM>(W2 + eo, g_W2f + eo);
    }
}

// ---------------- shared GEMM smem ----------------
struct GS {
    uint16_t A[2][TILE_U16];
    uint16_t B[2][TILE_U16];
    int   toks[BM];
    float gates[BM];
    float bias[BN];
};
#define GS_BYTES sizeof(GS)

// compute one k64 chunk from stage st
__device__ __forceinline__ void compute_chunk(GS* gs, int st, int wm, int wn, int lid,
                                              float acc[4][4][4]) {
    const int r_ = lid & 7, mat = lid >> 3;
    uint32_t pA = smem_u32(gs->A[st]);
    uint32_t pB = smem_u32(gs->B[st]);
#pragma unroll
    for (int s = 0; s < 4; s++) {               // 4 k16 steps
        uint32_t bf[4][2];
#pragma unroll
        for (int np = 0; np < 2; np++) {
            int row = wn * 32 + np * 16 + ((mat >> 1) << 3) + r_;
            int seg = (s << 1) | (mat & 1);
            uint32_t t[4];
            ldsm4(t, pB + sw_off(row, seg));
            bf[np * 2][0]     = t[0]; bf[np * 2][1]     = t[1];
            bf[np * 2 + 1][0] = t[2]; bf[np * 2 + 1][1] = t[3];
        }
#pragma unroll
        for (int mi = 0; mi < 4; mi++) {
            int row = wm * 64 + mi * 16 + ((mat & 1) << 3) + r_;
            int seg = (s << 1) | (mat >> 1);
            uint32_t af[4];
            ldsm4(af, pA + sw_off(row, seg));
#pragma unroll
            for (int ni = 0; ni < 4; ni++)
                mma16816(acc[mi][ni], af, bf[ni]);
        }
    }
}

// fill one stage: A gathered by tok list, B linear
__device__ __forceinline__ void fill_stage(GS* gs, int st, int tid,
                                           const uint16_t* __restrict__ A,
                                           const uint16_t* __restrict__ B,
                                           int k0, int lda, int ldb, bool gatherA, int mrem) {
    uint32_t pA = smem_u32(gs->A[st]);
    uint32_t pB = smem_u32(gs->B[st]);
#pragma unroll
    for (int i = 0; i < 4; i++) {
        int id  = tid + i * 256;   // 0..1023
        int row = id >> 3, seg = id & 7;
        uint32_t d = sw_off(row, seg);
        int vs; size_t grow;
        if (gatherA) {
            int tok = gs->toks[row];
            vs = (tok >= 0) ? 16 : 0;
            grow = (tok >= 0) ? (size_t)tok : 0;
        } else {
            vs = (row < mrem) ? 16 : 0;
            grow = (row < mrem) ? (size_t)row : 0;
        }
        cpa16(pA + d, A + grow * lda + k0 + seg * 8, vs);
        cpa16(pB + d, B + (size_t)row * ldb + k0 + seg * 8, 16);
    }
}

// ---------------- 4) GEMM1: H = relu(gather(x) @ W1 + b1) ----------------
__global__ __launch_bounds__(256, 2)
void gemm1_mma(const float* __restrict__ b1) {
    extern __shared__ __align__(16) char smraw[];
    GS* gs = (GS*)smraw;
    const int e   = blockIdx.z;
    const int cnt = g_cnt[e];
    const int m0  = blockIdx.x * BM;
    if (m0 >= cnt) return;
    const int n0   = blockIdx.y * BN;
    const int off  = g_off[e];
    const int mrem = cnt - m0;
    const int tid  = threadIdx.x;
    const int wid  = tid >> 5, lid = tid & 31;
    const int wm = wid >> 2, wn = wid & 3;
    const int g = lid >> 2, q = lid & 3;

    if (tid < BM) {
        gs->toks[tid] = (tid < mrem) ? g_tok[off + m0 + tid] : -1;
        gs->bias[tid] = b1[(size_t)e * H_DIM + n0 + tid];
    }
    __syncthreads();

    float acc[4][4][4];
#pragma unroll
    for (int a = 0; a < 4; a++)
#pragma unroll
        for (int b = 0; b < 4; b++)
#pragma unroll
            for (int c = 0; c < 4; c++) acc[a][b][c] = 0.f;

    const uint16_t* Bp = g_W1f + ((size_t)e * H_DIM + n0) * D_DIM;

    const int NC = D_DIM / BK;   // 8
    fill_stage(gs, 0, tid, g_Xf, Bp, 0, D_DIM, D_DIM, true, mrem);
    CP_COMMIT();
    for (int c = 0; c < NC; c++) {
        int st = c & 1;
        if (c + 1 < NC) {
            fill_stage(gs, st ^ 1, tid, g_Xf, Bp, (c + 1) * BK, D_DIM, D_DIM, true, mrem);
            CP_COMMIT();
            CP_WAIT(1);
        } else {
            CP_WAIT(0);
        }
        __syncthreads();
        compute_chunk(gs, st, wm, wn, lid, acc);
        __syncthreads();
    }

    // epilogue: bias + relu -> fp16 H
#pragma unroll
    for (int mi = 0; mi < 4; mi++) {
#pragma unroll
        for (int h = 0; h < 2; h++) {
            int mrow = wm * 64 + mi * 16 + g + h * 8;
            if (mrow < mrem) {
                size_t rb = (size_t)(off + m0 + mrow) * H_DIM + n0;
#pragma unroll
                for (int ni = 0; ni < 4; ni++) {
                    int n = wn * 32 + ni * 8 + q * 2;
                    float v0 = fmaxf(acc[mi][ni][h * 2 + 0] + gs->bias[n], 0.f);
                    float v1 = fmaxf(acc[mi][ni][h * 2 + 1] + gs->bias[n + 1], 0.f);
                    *(uint32_t*)(g_Hf + rb + n) = packh2(v0, v1);
                }
            }
        }
    }
}

// ---------------- 5) GEMM2: out += gate * (H @ W2 + b2) ----------------
__global__ __launch_bounds__(256, 2)
void gemm2_mma(const float* __restrict__ b2, float* __restrict__ out) {
    extern __shared__ __align__(16) char smraw[];
    GS* gs = (GS*)smraw;
    const int e   = blockIdx.z;
    const int cnt = g_cnt[e];
    const int m0  = blockIdx.x * BM;
    if (m0 >= cnt) return;
    const int n0   = blockIdx.y * BN;
    const int off  = g_off[e];
    const int mrem = cnt - m0;
    const int tid  = threadIdx.x;
    const int wid  = tid >> 5, lid = tid & 31;
    const int wm = wid >> 2, wn = wid & 3;
    const int g = lid >> 2, q = lid & 3;

    if (tid < BM) {
        int valid = tid < mrem;
        int s = off + m0 + tid;
        gs->toks[tid]  = valid ? g_tok[s] : -1;
        gs->gates[tid] = valid ? g_gate[s] : 0.f;
        gs->bias[tid]  = b2[(size_t)e * D_DIM + n0 + tid];
    }
    __syncthreads();

    float acc[4][4][4];
#pragma unroll
    for (int a = 0; a < 4; a++)
#pragma unroll
        for (int b = 0; b < 4; b++)
#pragma unroll
            for (int c = 0; c < 4; c++) acc[a][b][c] = 0.f;

    const uint16_t* Ap = g_Hf + (size_t)(off + m0) * H_DIM;
    const uint16_t* Bp = g_W2f + ((size_t)e * D_DIM + n0) * H_DIM;

    const int NC = H_DIM / BK;   // 16
    fill_stage(gs, 0, tid, Ap, Bp, 0, H_DIM, H_DIM, false, mrem);
    CP_COMMIT();
    for (int c = 0; c < NC; c++) {
        int st = c & 1;
        if (c + 1 < NC) {
            fill_stage(gs, st ^ 1, tid, Ap, Bp, (c + 1) * BK, H_DIM, H_DIM, false, mrem);
            CP_COMMIT();
            CP_WAIT(1);
        } else {
            CP_WAIT(0);
        }
        __syncthreads();
        compute_chunk(gs, st, wm, wn, lid, acc);
        __syncthreads();
    }

    // epilogue: (acc + bias) * gate -> atomicAdd combine
#pragma unroll
    for (int mi = 0; mi < 4; mi++) {
#pragma unroll
        for (int h = 0; h < 2; h++) {
            int mrow = wm * 64 + mi * 16 + g + h * 8;
            if (mrow < mrem) {
                int tok  = gs->toks[mrow];
                float gt = gs->gates[mrow];
                float* dst = out + (size_t)tok * D_DIM + n0;
#pragma unroll
                for (int ni = 0; ni < 4; ni++) {
                    int n = wn * 32 + ni * 8 + q * 2;
                    atomicAdd(&dst[n],     (acc[mi][ni][h * 2 + 0] + gs->bias[n]) * gt);
                    atomicAdd(&dst[n + 1], (acc[mi][ni][h * 2 + 1] + gs->bias[n + 1]) * gt);
                }
            }
        }
    }
}

// ---------------- launch ----------------
extern "C" void kernel_launch(void* const* d_in, const int* in_sizes, int n_in,
                              void* d_out, int out_size) {
    const float* x  = (const float*)d_in[0];
    const float* Wg = (const float*)d_in[1];
    const float* W1 = (const float*)d_in[2];
    const float* b1 = (const float*)d_in[3];
    const float* W2 = (const float*)d_in[4];
    const float* b2 = (const float*)d_in[5];
    float* out = (float*)d_out;

    // one-time setup on the first (uncaptured correctness) call
    static cudaStream_t s2 = nullptr;
    static cudaEvent_t evFork = nullptr, evJoin = nullptr;
    static bool init_done = false;
    if (!init_done) {
        cudaFuncSetAttribute(gemm1_mma, cudaFuncAttributeMaxDynamicSharedMemorySize, (int)GS_BYTES);
        cudaFuncSetAttribute(gemm2_mma, cudaFuncAttributeMaxDynamicSharedMemorySize, (int)GS_BYTES);
        cudaStreamCreateWithFlags(&s2, cudaStreamNonBlocking);
        cudaEventCreateWithFlags(&evFork, cudaEventDisableTiming);
        cudaEventCreateWithFlags(&evJoin, cudaEventDisableTiming);
        init_done = true;
    }

    // fork: weight conversion (depends only on W1/W2) runs on s2
    cudaEventRecord(evFork, 0);
    cudaStreamWaitEvent(s2, evFork, 0);
    conv_w_kernel<<<dim3(32, 32, 2 * E_NUM), dim3(32, 8), 0, s2>>>(W1, W2);
    cudaEventRecord(evJoin, s2);

    // main stream: gating path
    cudaMemsetAsync(out, 0, (size_t)T_TOK * D_DIM * sizeof(float));
    gate_kernel<<<T_TOK / 128, 128>>>(x, Wg);
    setup_kernel<<<1, 256>>>(out);
    scatter_kernel<<<(T_TOK + 255) / 256, 256>>>();

    // join before GEMMs
    cudaStreamWaitEvent(0, evJoin, 0);

    dim3 g1(T_TOK / BM, H_DIM / BN, E_NUM);   // (64, 8, 8), empty tiles exit
    gemm1_mma<<<g1, 256, GS_BYTES>>>(b1);

    dim3 g2(T_TOK / BM, D_DIM / BN, E_NUM);   // (64, 4, 8)
    gemm2_mma<<<g2, 256, GS_BYTES>>>(b2, out);
}

// round 11
// speedup vs baseline: 1.5484x; 1.0831x over previous
#include <cuda_runtime.h>
#include <cuda_bf16.h>
#include <cuda_fp16.h>
#include <cstdint>
#include <math.h>

// Problem constants (fixed shapes)
#define T_TOK 8192
#define D_DIM 512
#define H_DIM 1024
#define E_NUM 8
#define K_TOP 2
#define PAIRS (T_TOK * K_TOP)   // 16384

// GEMM tile config
#define BM 128
#define BN 128
#define BK 64
#define TILE_U16 (BM * BK)      // 8192 fp16 per tile (16KB)

// ---------------- device scratch (no allocations allowed) ----------------
__device__ uint16_t g_Xf[(size_t)T_TOK * D_DIM];             // x as fp16 bits
__device__ uint16_t g_Hf[(size_t)PAIRS * H_DIM];             // activations fp16
__device__ uint16_t g_W1f[(size_t)E_NUM * H_DIM * D_DIM];    // W1^T [E][H][D] fp16
__device__ uint16_t g_W2f[(size_t)E_NUM * D_DIM * H_DIM];    // W2^T [E][D][H] fp16
__device__ int   g_e0[T_TOK], g_e1[T_TOK];
__device__ float g_g0[T_TOK], g_g1[T_TOK];

// aggregation block: zeroed once per launch by a single memset
struct Agg {
    int   cnt[E_NUM];
    float imp[E_NUM];
    int   cursor[E_NUM];
};
__device__ Agg g_agg;
__device__ int   g_off[E_NUM];
__device__ int   g_tok[PAIRS];
__device__ float g_gate[PAIRS];

// ---------------- helpers ----------------
__device__ __forceinline__ uint32_t smem_u32(const void* p) {
    uint32_t a;
    asm("{ .reg .u64 t; cvta.to.shared.u64 t, %1; cvt.u32.u64 %0, t; }" : "=r"(a) : "l"(p));
    return a;
}
__device__ __forceinline__ uint32_t packh2(float a, float b) {
    __half2 h = __floats2half2_rn(a, b);
    return *(uint32_t*)&h;
}

// mma.sync m16n8k16 fp16 (row.col), fp32 accum
__device__ __forceinline__ void mma16816(float* c, const uint32_t* a, const uint32_t* b) {
    asm volatile(
        "mma.sync.aligned.m16n8k16.row.col.f32.f16.f16.f32 "
        "{%0,%1,%2,%3}, {%4,%5,%6,%7}, {%8,%9}, {%0,%1,%2,%3};\n"
        : "+f"(c[0]), "+f"(c[1]), "+f"(c[2]), "+f"(c[3])
        : "r"(a[0]), "r"(a[1]), "r"(a[2]), "r"(a[3]), "r"(b[0]), "r"(b[1]));
}
__device__ __forceinline__ void ldsm4(uint32_t* r, uint32_t a) {
    asm volatile("ldmatrix.sync.aligned.m8n8.x4.shared.b16 {%0,%1,%2,%3}, [%4];"
        : "=r"(r[0]), "=r"(r[1]), "=r"(r[2]), "=r"(r[3]) : "r"(a));
}
__device__ __forceinline__ void cpa16(uint32_t dst, const void* src, int srcsz) {
    asm volatile("cp.async.cg.shared.global [%0], [%1], 16, %2;"
        :: "r"(dst), "l"(src), "r"(srcsz) : "memory");
}
#define CP_COMMIT() asm volatile("cp.async.commit_group;" ::: "memory")
#define CP_WAIT(n)  asm volatile("cp.async.wait_group %0;" :: "n"(n) : "memory")

// smem tile byte offset: 128B rows (64 fp16), seg = 16B segment (0..7), XOR swizzle
__device__ __forceinline__ uint32_t sw_off(int row, int seg) {
    return (uint32_t)(row * 128 + ((seg ^ (row & 7)) << 4));
}

// ---------------- 1) gating: logits, top-2, softmax; emits x fp16 ----------
// also block-aggregates per-expert counts (int, exact) and importance (float)
__global__ void gate_kernel(const float* __restrict__ x,
                            const float* __restrict__ Wg) {
    __shared__ float xs[128][68];
    __shared__ float wgs[64][8];
    __shared__ int   s_cnt[E_NUM];
    __shared__ float s_imp[E_NUM];
    const int tid = threadIdx.x;
    const int t0  = blockIdx.x * 128;
    if (tid < E_NUM) { s_cnt[tid] = 0; s_imp[tid] = 0.f; }
    float acc[E_NUM];
#pragma unroll
    for (int e = 0; e < E_NUM; e++) acc[e] = 0.f;

    for (int k0 = 0; k0 < D_DIM; k0 += 64) {
#pragma unroll
        for (int i = 0; i < 4; i++) {
            int idx = tid + i * 128;
            wgs[idx >> 3][idx & 7] = Wg[(k0 + (idx >> 3)) * E_NUM + (idx & 7)];
        }
#pragma unroll
        for (int i = 0; i < 16; i++) {
            int f4  = i * 128 + tid;
            int row = f4 >> 4;
            int c4  = f4 & 15;
            float4 v = *(const float4*)(x + (size_t)(t0 + row) * D_DIM + k0 + c4 * 4);
            *(float4*)&xs[row][c4 * 4] = v;
            size_t o = (size_t)(t0 + row) * D_DIM + k0 + c4 * 4;
            *(uint2*)(g_Xf + o) = make_uint2(packh2(v.x, v.y), packh2(v.z, v.w));
        }
        __syncthreads();
#pragma unroll 8
        for (int k = 0; k < 64; k++) {
            float xv = xs[tid][k];
#pragma unroll
            for (int e = 0; e < E_NUM; e++) acc[e] = fmaf(xv, wgs[k][e], acc[e]);
        }
        __syncthreads();
    }
    int e0 = 0; float v0 = acc[0];
#pragma unroll
    for (int e = 1; e < E_NUM; e++) if (acc[e] > v0) { v0 = acc[e]; e0 = e; }
    int e1 = -1; float v1 = -INFINITY;
#pragma unroll
    for (int e = 0; e < E_NUM; e++) if (e != e0 && acc[e] > v1) { v1 = acc[e]; e1 = e; }
    float p1 = __expf(v1 - v0);
    float inv = 1.f / (1.f + p1);
    float gv0 = inv, gv1 = p1 * inv;
    int t = t0 + tid;
    g_e0[t] = e0; g_e1[t] = e1;
    g_g0[t] = gv0; g_g1[t] = gv1;

    // block aggregation -> global
    atomicAdd(&s_cnt[e0], 1);
    atomicAdd(&s_cnt[e1], 1);
    atomicAdd(&s_imp[e0], gv0);
    atomicAdd(&s_imp[e1], gv1);
    __syncthreads();
    if (tid < E_NUM) {
        atomicAdd(&g_agg.cnt[tid], s_cnt[tid]);
        atomicAdd(&g_agg.imp[tid], s_imp[tid]);
    }
}

// ---------------- 2) setup: offsets + losses from pre-reduced sums ----------
__global__ void setup_kernel(float* __restrict__ out) {
    if (threadIdx.x != 0) return;
    const float eps = 1e-10f;
    int off = 0;
    float mi = 0.f, ml = 0.f;
    int cnts[E_NUM]; float imps[E_NUM];
#pragma unroll
    for (int e = 0; e < E_NUM; e++) {
        cnts[e] = g_agg.cnt[e];
        imps[e] = g_agg.imp[e];
        g_off[e] = off;
        off += cnts[e];
        mi += imps[e];
        ml += (float)cnts[e];
    }
    mi /= E_NUM; ml /= E_NUM;
    float vi = 0.f, vl = 0.f;
#pragma unroll
    for (int e = 0; e < E_NUM; e++) {
        float di = imps[e] - mi; vi += di * di;
        float dl = (float)cnts[e] - ml; vl += dl * dl;
    }
    vi /= (E_NUM - 1); vl /= (E_NUM - 1);
    out[(size_t)T_TOK * D_DIM]     = vi / (mi * mi + eps);
    out[(size_t)T_TOK * D_DIM + 1] = vl / (ml * ml + eps);
}

// ---------------- 3) scatter (hierarchical atomics) ----------------
__global__ void scatter_kernel() {
    __shared__ int s_cnt[E_NUM];
    __shared__ int s_base[E_NUM];
    const int tid = threadIdx.x;
    if (tid < E_NUM) s_cnt[tid] = 0;
    __syncthreads();
    int t = blockIdx.x * 256 + tid;
    int e0 = g_e0[t], e1 = g_e1[t];
    int r0 = atomicAdd(&s_cnt[e0], 1);
    int r1 = atomicAdd(&s_cnt[e1], 1);
    __syncthreads();
    if (tid < E_NUM) s_base[tid] = atomicAdd(&g_agg.cursor[tid], s_cnt[tid]);
    __syncthreads();
    {
        int s = g_off[e0] + s_base[e0] + r0;
        g_tok[s] = t; g_gate[s] = g_g0[t];
    }
    {
        int s = g_off[e1] + s_base[e1] + r1;
        g_tok[s] = t; g_gate[s] = g_g1[t];
    }
}

// ------------- weight transpose + fp16 convert (fused W1+W2) -------------
template <int R, int C>
__device__ __forceinline__ void transpose_half(const float* __restrict__ s,
                                               uint16_t* __restrict__ d) {
    __shared__ float tile[32][33];
    int c0 = blockIdx.x * 32, r0 = blockIdx.y * 32;
#pragma unroll
    for (int i = 0; i < 32; i += 8)
        tile[threadIdx.y + i][threadIdx.x] = s[(size_t)(r0 + threadIdx.y + i) * C + c0 + threadIdx.x];
    __syncthreads();
#pragma unroll
    for (int i = 0; i < 32; i += 8) {
        float v = tile[threadIdx.x][threadIdx.y + i];
        __half h = __float2half_rn(v);
        d[(size_t)(c0 + threadIdx.y + i) * R + r0 + threadIdx.x] = *(uint16_t*)&h;
    }
}
// grid: (32, 32, 2*E); per-branch bounds guards.
__global__ void conv_w_kernel(const float* __restrict__ W1,
                              const float* __restrict__ W2) {
    int z = blockIdx.z;
    if (z < E_NUM) {
        if (blockIdx.x >= H_DIM / 32 || blockIdx.y >= D_DIM / 32) return;
        size_t eo = (size_t)z * D_DIM * H_DIM;
        transpose_half<D_DIM, H_DIM>(W1 + eo, g_W1f + eo);
    } else {
        if (blockIdx.x >= D_DIM / 32 || blockIdx.y >= H_DIM / 32) return;
        size_t eo = (size_t)(z - E_NUM) * H_DIM * D_DIM;
        transpose_half<H_DIM, D_DIM>(W2 + eo, g_W2f + eo);
    }
}

// ---------------- shared GEMM smem ----------------
struct GS {
    uint16_t A[2][TILE_U16];
    uint16_t B[2][TILE_U16];
    int   toks[BM];
    float gates[BM];
    float bias[BN];
};
#define GS_BYTES sizeof(GS)

// compute one k64 chunk from stage st
__device__ __forceinline__ void compute_chunk(GS* gs, int st, int wm, int wn, int lid,
                                              float acc[4][4][4]) {
    const int r_ = lid & 7, mat = lid >> 3;
    uint32_t pA = smem_u32(gs->A[st]);
    uint32_t pB = smem_u32(gs->B[st]);
#pragma unroll
    for (int s = 0; s < 4; s++) {               // 4 k16 steps
        uint32_t bf[4][2];
#pragma unroll
        for (int np = 0; np < 2; np++) {
            int row = wn * 32 + np * 16 + ((mat >> 1) << 3) + r_;
            int seg = (s << 1) | (mat & 1);
            uint32_t t[4];
            ldsm4(t, pB + sw_off(row, seg));
            bf[np * 2][0]     = t[0]; bf[np * 2][1]     = t[1];
            bf[np * 2 + 1][0] = t[2]; bf[np * 2 + 1][1] = t[3];
        }
#pragma unroll
        for (int mi = 0; mi < 4; mi++) {
            int row = wm * 64 + mi * 16 + ((mat & 1) << 3) + r_;
            int seg = (s << 1) | (mat >> 1);
            uint32_t af[4];
            ldsm4(af, pA + sw_off(row, seg));
#pragma unroll
            for (int ni = 0; ni < 4; ni++)
                mma16816(acc[mi][ni], af, bf[ni]);
        }
    }
}

// fill one stage: A gathered by tok list, B linear
__device__ __forceinline__ void fill_stage(GS* gs, int st, int tid,
                                           const uint16_t* __restrict__ A,
                                           const uint16_t* __restrict__ B,
                                           int k0, int lda, int ldb, bool gatherA, int mrem) {
    uint32_t pA = smem_u32(gs->A[st]);
    uint32_t pB = smem_u32(gs->B[st]);
#pragma unroll
    for (int i = 0; i < 4; i++) {
        int id  = tid + i * 256;   // 0..1023
        int row = id >> 3, seg = id & 7;
        uint32_t d = sw_off(row, seg);
        int vs; size_t grow;
        if (gatherA) {
            int tok = gs->toks[row];
            vs = (tok >= 0) ? 16 : 0;
            grow = (tok >= 0) ? (size_t)tok : 0;
        } else {
            vs = (row < mrem) ? 16 : 0;
            grow = (row < mrem) ? (size_t)row : 0;
        }
        cpa16(pA + d, A + grow * lda + k0 + seg * 8, vs);
        cpa16(pB + d, B + (size_t)row * ldb + k0 + seg * 8, 16);
    }
}

// ---------------- 4) GEMM1: H = relu(gather(x) @ W1 + b1) ----------------
__global__ __launch_bounds__(256, 2)
void gemm1_mma(const float* __restrict__ b1) {
    extern __shared__ __align__(16) char smraw[];
    GS* gs = (GS*)smraw;
    const int e   = blockIdx.z;
    const int cnt = g_agg.cnt[e];
    const int m0  = blockIdx.x * BM;
    if (m0 >= cnt) return;
    const int n0   = blockIdx.y * BN;
    const int off  = g_off[e];
    const int mrem = cnt - m0;
    const int tid  = threadIdx.x;
    const int wid  = tid >> 5, lid = tid & 31;
    const int wm = wid >> 2, wn = wid & 3;
    const int g = lid >> 2, q = lid & 3;

    if (tid < BM) {
        gs->toks[tid] = (tid < mrem) ? g_tok[off + m0 + tid] : -1;
        gs->bias[tid] = b1[(size_t)e * H_DIM + n0 + tid];
    }
    __syncthreads();

    float acc[4][4][4];
#pragma unroll
    for (int a = 0; a < 4; a++)
#pragma unroll
        for (int b = 0; b < 4; b++)
#pragma unroll
            for (int c = 0; c < 4; c++) acc[a][b][c] = 0.f;

    const uint16_t* Bp = g_W1f + ((size_t)e * H_DIM + n0) * D_DIM;

    const int NC = D_DIM / BK;   // 8
    fill_stage(gs, 0, tid, g_Xf, Bp, 0, D_DIM, D_DIM, true, mrem);
    CP_COMMIT();
    for (int c = 0; c < NC; c++) {
        int st = c & 1;
        if (c + 1 < NC) {
            fill_stage(gs, st ^ 1, tid, g_Xf, Bp, (c + 1) * BK, D_DIM, D_DIM, true, mrem);
            CP_COMMIT();
            CP_WAIT(1);
        } else {
            CP_WAIT(0);
        }
        __syncthreads();
        compute_chunk(gs, st, wm, wn, lid, acc);
        __syncthreads();
    }

    // epilogue: bias + relu -> fp16 H
#pragma unroll
    for (int mi = 0; mi < 4; mi++) {
#pragma unroll
        for (int h = 0; h < 2; h++) {
            int mrow = wm * 64 + mi * 16 + g + h * 8;
            if (mrow < mrem) {
                size_t rb = (size_t)(off + m0 + mrow) * H_DIM + n0;
#pragma unroll
                for (int ni = 0; ni < 4; ni++) {
                    int n = wn * 32 + ni * 8 + q * 2;
                    float v0 = fmaxf(acc[mi][ni][h * 2 + 0] + gs->bias[n], 0.f);
                    float v1 = fmaxf(acc[mi][ni][h * 2 + 1] + gs->bias[n + 1], 0.f);
                    *(uint32_t*)(g_Hf + rb + n) = packh2(v0, v1);
                }
            }
        }
    }
}

// ---------------- 5) GEMM2: out += gate * (H @ W2 + b2) ----------------
__global__ __launch_bounds__(256, 2)
void gemm2_mma(const float* __restrict__ b2, float* __restrict__ out) {
    extern __shared__ __align__(16) char smraw[];
    GS* gs = (GS*)smraw;
    const int e   = blockIdx.z;
    const int cnt = g_agg.cnt[e];
    const int m0  = blockIdx.x * BM;
    if (m0 >= cnt) return;
    const int n0   = blockIdx.y * BN;
    const int off  = g_off[e];
    const int mrem = cnt - m0;
    const int tid  = threadIdx.x;
    const int wid  = tid >> 5, lid = tid & 31;
    const int wm = wid >> 2, wn = wid & 3;
    const int g = lid >> 2, q = lid & 3;

    if (tid < BM) {
        int valid = tid < mrem;
        int s = off + m0 + tid;
        gs->toks[tid]  = valid ? g_tok[s] : -1;
        gs->gates[tid] = valid ? g_gate[s] : 0.f;
        gs->bias[tid]  = b2[(size_t)e * D_DIM + n0 + tid];
    }
    __syncthreads();

    float acc[4][4][4];
#pragma unroll
    for (int a = 0; a < 4; a++)
#pragma unroll
        for (int b = 0; b < 4; b++)
#pragma unroll
            for (int c = 0; c < 4; c++) acc[a][b][c] = 0.f;

    const uint16_t* Ap = g_Hf + (size_t)(off + m0) * H_DIM;
    const uint16_t* Bp = g_W2f + ((size_t)e * D_DIM + n0) * H_DIM;

    const int NC = H_DIM / BK;   // 16
    fill_stage(gs, 0, tid, Ap, Bp, 0, H_DIM, H_DIM, false, mrem);
    CP_COMMIT();
    for (int c = 0; c < NC; c++) {
        int st = c & 1;
        if (c + 1 < NC) {
            fill_stage(gs, st ^ 1, tid, Ap, Bp, (c + 1) * BK, H_DIM, H_DIM, false, mrem);
            CP_COMMIT();
            CP_WAIT(1);
        } else {
            CP_WAIT(0);
        }
        __syncthreads();
        compute_chunk(gs, st, wm, wn, lid, acc);
        __syncthreads();
    }

    // epilogue: (acc + bias) * gate -> float2 vector atomicAdd combine
#pragma unroll
    for (int mi = 0; mi < 4; mi++) {
#pragma unroll
        for (int h = 0; h < 2; h++) {
            int mrow = wm * 64 + mi * 16 + g + h * 8;
            if (mrow < mrem) {
                int tok  = gs->toks[mrow];
                float gt = gs->gates[mrow];
                float* dst = out + (size_t)tok * D_DIM + n0;
#pragma unroll
                for (int ni = 0; ni < 4; ni++) {
                    int n = wn * 32 + ni * 8 + q * 2;
                    float2 v = make_float2((acc[mi][ni][h * 2 + 0] + gs->bias[n]) * gt,
                                           (acc[mi][ni][h * 2 + 1] + gs->bias[n + 1]) * gt);
                    atomicAdd(reinterpret_cast<float2*>(dst + n), v);
                }
            }
        }
    }
}

// ---------------- launch ----------------
extern "C" void kernel_launch(void* const* d_in, const int* in_sizes, int n_in,
                              void* d_out, int out_size) {
    const float* x  = (const float*)d_in[0];
    const float* Wg = (const float*)d_in[1];
    const float* W1 = (const float*)d_in[2];
    const float* b1 = (const float*)d_in[3];
    const float* W2 = (const float*)d_in[4];
    const float* b2 = (const float*)d_in[5];
    float* out = (float*)d_out;

    // one-time setup on the first (uncaptured correctness) call
    static cudaStream_t s2 = nullptr;
    static cudaEvent_t evFork = nullptr, evJoin = nullptr;
    static void* aggPtr = nullptr;
    static bool init_done = false;
    if (!init_done) {
        cudaFuncSetAttribute(gemm1_mma, cudaFuncAttributeMaxDynamicSharedMemorySize, (int)GS_BYTES);
        cudaFuncSetAttribute(gemm2_mma, cudaFuncAttributeMaxDynamicSharedMemorySize, (int)GS_BYTES);
        cudaStreamCreateWithFlags(&s2, cudaStreamNonBlocking);
        cudaEventCreateWithFlags(&evFork, cudaEventDisableTiming);
        cudaEventCreateWithFlags(&evJoin, cudaEventDisableTiming);
        cudaGetSymbolAddress(&aggPtr, g_agg);
        init_done = true;
    }

    // fork: weight conversion (depends only on W1/W2) runs on s2
    cudaEventRecord(evFork, 0);
    cudaStreamWaitEvent(s2, evFork, 0);
    conv_w_kernel<<<dim3(32, 32, 2 * E_NUM), dim3(32, 8), 0, s2>>>(W1, W2);
    cudaEventRecord(evJoin, s2);

    // main stream: gating path
    cudaMemsetAsync(aggPtr, 0, sizeof(Agg));
    cudaMemsetAsync(out, 0, (size_t)T_TOK * D_DIM * sizeof(float));
    gate_kernel<<<T_TOK / 128, 128>>>(x, Wg);
    setup_kernel<<<1, 32>>>(out);
    scatter_kernel<<<T_TOK / 256, 256>>>();

    // join before GEMMs
    cudaStreamWaitEvent(0, evJoin, 0);

    dim3 g1(T_TOK / BM, H_DIM / BN, E_NUM);   // (64, 8, 8), empty tiles exit
    gemm1_mma<<<g1, 256, GS_BYTES>>>(b1);

    dim3 g2(T_TOK / BM, D_DIM / BN, E_NUM);   // (64, 4, 8)
    gemm2_mma<<<g2, 256, GS_BYTES>>>(b2, out);
}

// round 12
// speedup vs baseline: 1.5986x; 1.0324x over previous
#include <cuda_runtime.h>
#include <cuda_bf16.h>
#include <cuda_fp16.h>
#include <cstdint>
#include <math.h>

// Problem constants (fixed shapes)
#define T_TOK 8192
#define D_DIM 512
#define H_DIM 1024
#define E_NUM 8
#define K_TOP 2
#define PAIRS (T_TOK * K_TOP)   // 16384

// GEMM tile config
#define BM 128
#define BN 128
#define BK 64
#define TILE_U16 (BM * BK)      // 8192 fp16 per tile (16KB)

// ---------------- device scratch (no allocations allowed) ----------------
__device__ uint16_t g_Xf[(size_t)T_TOK * D_DIM];                  // x as fp16 bits
__device__ uint16_t g_Hf[(size_t)E_NUM * T_TOK * H_DIM];          // activations fp16 (per-expert regions)
__device__ uint16_t g_W1f[(size_t)E_NUM * H_DIM * D_DIM];         // W1^T [E][H][D] fp16
__device__ uint16_t g_W2f[(size_t)E_NUM * D_DIM * H_DIM];         // W2^T [E][D][H] fp16

// aggregation block: zeroed once per launch by a single memset
struct Agg {
    float imp[E_NUM];
    int   cursor[E_NUM];     // final value == per-expert count
};
__device__ Agg g_agg;
__device__ int   g_tok[(size_t)E_NUM * T_TOK];    // fixed-capacity per-expert lists
__device__ float g_gate[(size_t)E_NUM * T_TOK];

// ---------------- helpers ----------------
__device__ __forceinline__ uint32_t smem_u32(const void* p) {
    uint32_t a;
    asm("{ .reg .u64 t; cvta.to.shared.u64 t, %1; cvt.u32.u64 %0, t; }" : "=r"(a) : "l"(p));
    return a;
}
__device__ __forceinline__ uint32_t packh2(float a, float b) {
    __half2 h = __floats2half2_rn(a, b);
    return *(uint32_t*)&h;
}

// mma.sync m16n8k16 fp16 (row.col), fp32 accum
__device__ __forceinline__ void mma16816(float* c, const uint32_t* a, const uint32_t* b) {
    asm volatile(
        "mma.sync.aligned.m16n8k16.row.col.f32.f16.f16.f32 "
        "{%0,%1,%2,%3}, {%4,%5,%6,%7}, {%8,%9}, {%0,%1,%2,%3};\n"
        : "+f"(c[0]), "+f"(c[1]), "+f"(c[2]), "+f"(c[3])
        : "r"(a[0]), "r"(a[1]), "r"(a[2]), "r"(a[3]), "r"(b[0]), "r"(b[1]));
}
__device__ __forceinline__ void ldsm4(uint32_t* r, uint32_t a) {
    asm volatile("ldmatrix.sync.aligned.m8n8.x4.shared.b16 {%0,%1,%2,%3}, [%4];"
        : "=r"(r[0]), "=r"(r[1]), "=r"(r[2]), "=r"(r[3]) : "r"(a));
}
__device__ __forceinline__ void cpa16(uint32_t dst, const void* src, int srcsz) {
    asm volatile("cp.async.cg.shared.global [%0], [%1], 16, %2;"
        :: "r"(dst), "l"(src), "r"(srcsz) : "memory");
}
#define CP_COMMIT() asm volatile("cp.async.commit_group;" ::: "memory")
#define CP_WAIT(n)  asm volatile("cp.async.wait_group %0;" :: "n"(n) : "memory")

// smem tile byte offset: 128B rows (64 fp16), seg = 16B segment (0..7), XOR swizzle
__device__ __forceinline__ uint32_t sw_off(int row, int seg) {
    return (uint32_t)(row * 128 + ((seg ^ (row & 7)) << 4));
}

// ---------------- 1) gating: logits, top-2, softmax; emits x fp16;
//                    fused scatter into fixed-capacity expert lists ----------
__global__ void gate_kernel(const float* __restrict__ x,
                            const float* __restrict__ Wg) {
    __shared__ float xs[128][68];
    __shared__ float wgs[64][8];
    __shared__ int   s_cnt[E_NUM];
    __shared__ int   s_base[E_NUM];
    __shared__ float s_imp[E_NUM];
    const int tid = threadIdx.x;
    const int t0  = blockIdx.x * 128;
    if (tid < E_NUM) { s_cnt[tid] = 0; s_imp[tid] = 0.f; }
    float acc[E_NUM];
#pragma unroll
    for (int e = 0; e < E_NUM; e++) acc[e] = 0.f;

    for (int k0 = 0; k0 < D_DIM; k0 += 64) {
#pragma unroll
        for (int i = 0; i < 4; i++) {
            int idx = tid + i * 128;
            wgs[idx >> 3][idx & 7] = Wg[(k0 + (idx >> 3)) * E_NUM + (idx & 7)];
        }
#pragma unroll
        for (int i = 0; i < 16; i++) {
            int f4  = i * 128 + tid;
            int row = f4 >> 4;
            int c4  = f4 & 15;
            float4 v = *(const float4*)(x + (size_t)(t0 + row) * D_DIM + k0 + c4 * 4);
            *(float4*)&xs[row][c4 * 4] = v;
            size_t o = (size_t)(t0 + row) * D_DIM + k0 + c4 * 4;
            *(uint2*)(g_Xf + o) = make_uint2(packh2(v.x, v.y), packh2(v.z, v.w));
        }
        __syncthreads();
#pragma unroll 8
        for (int k = 0; k < 64; k++) {
            float xv = xs[tid][k];
#pragma unroll
            for (int e = 0; e < E_NUM; e++) acc[e] = fmaf(xv, wgs[k][e], acc[e]);
        }
        __syncthreads();
    }
    int e0 = 0; float v0 = acc[0];
#pragma unroll
    for (int e = 1; e < E_NUM; e++) if (acc[e] > v0) { v0 = acc[e]; e0 = e; }
    int e1 = -1; float v1 = -INFINITY;
#pragma unroll
    for (int e = 0; e < E_NUM; e++) if (e != e0 && acc[e] > v1) { v1 = acc[e]; e1 = e; }
    float p1 = __expf(v1 - v0);
    float inv = 1.f / (1.f + p1);
    float gv0 = inv, gv1 = p1 * inv;
    int t = t0 + tid;

    // fused scatter: block-local ranks, one cursor atomic per expert per block
    int r0 = atomicAdd(&s_cnt[e0], 1);
    int r1 = atomicAdd(&s_cnt[e1], 1);
    atomicAdd(&s_imp[e0], gv0);
    atomicAdd(&s_imp[e1], gv1);
    __syncthreads();
    if (tid < E_NUM) {
        s_base[tid] = atomicAdd(&g_agg.cursor[tid], s_cnt[tid]);
        atomicAdd(&g_agg.imp[tid], s_imp[tid]);
    }
    __syncthreads();
    {
        int s = e0 * T_TOK + s_base[e0] + r0;
        g_tok[s] = t; g_gate[s] = gv0;
    }
    {
        int s = e1 * T_TOK + s_base[e1] + r1;
        g_tok[s] = t; g_gate[s] = gv1;
    }
}

// ---------------- 2) setup: losses from pre-reduced sums ----------
__global__ void setup_kernel(float* __restrict__ out) {
    if (threadIdx.x != 0) return;
    const float eps = 1e-10f;
    float mi = 0.f, ml = 0.f;
    int cnts[E_NUM]; float imps[E_NUM];
#pragma unroll
    for (int e = 0; e < E_NUM; e++) {
        cnts[e] = g_agg.cursor[e];
        imps[e] = g_agg.imp[e];
        mi += imps[e];
        ml += (float)cnts[e];
    }
    mi /= E_NUM; ml /= E_NUM;
    float vi = 0.f, vl = 0.f;
#pragma unroll
    for (int e = 0; e < E_NUM; e++) {
        float di = imps[e] - mi; vi += di * di;
        float dl = (float)cnts[e] - ml; vl += dl * dl;
    }
    vi /= (E_NUM - 1); vl /= (E_NUM - 1);
    out[(size_t)T_TOK * D_DIM]     = vi / (mi * mi + eps);
    out[(size_t)T_TOK * D_DIM + 1] = vl / (ml * ml + eps);
}

// ------------- weight transpose + fp16 convert (fused W1+W2) -------------
template <int R, int C>
__device__ __forceinline__ void transpose_half(const float* __restrict__ s,
                                               uint16_t* __restrict__ d) {
    __shared__ float tile[32][33];
    int c0 = blockIdx.x * 32, r0 = blockIdx.y * 32;
#pragma unroll
    for (int i = 0; i < 32; i += 8)
        tile[threadIdx.y + i][threadIdx.x] = s[(size_t)(r0 + threadIdx.y + i) * C + c0 + threadIdx.x];
    __syncthreads();
#pragma unroll
    for (int i = 0; i < 32; i += 8) {
        float v = tile[threadIdx.x][threadIdx.y + i];
        __half h = __float2half_rn(v);
        d[(size_t)(c0 + threadIdx.y + i) * R + r0 + threadIdx.x] = *(uint16_t*)&h;
    }
}
// grid: (32, 32, 2*E); per-branch bounds guards.
__global__ void conv_w_kernel(const float* __restrict__ W1,
                              const float* __restrict__ W2) {
    int z = blockIdx.z;
    if (z < E_NUM) {
        if (blockIdx.x >= H_DIM / 32 || blockIdx.y >= D_DIM / 32) return;
        size_t eo = (size_t)z * D_DIM * H_DIM;
        transpose_half<D_DIM, H_DIM>(W1 + eo, g_W1f + eo);
    } else {
        if (blockIdx.x >= D_DIM / 32 || blockIdx.y >= H_DIM / 32) return;
        size_t eo = (size_t)(z - E_NUM) * H_DIM * D_DIM;
        transpose_half<H_DIM, D_DIM>(W2 + eo, g_W2f + eo);
    }
}

// ---------------- shared GEMM smem ----------------
struct GS {
    uint16_t A[2][TILE_U16];
    uint16_t B[2][TILE_U16];
    int   toks[BM];
    float gates[BM];
    float bias[BN];
};
#define GS_BYTES sizeof(GS)

// compute one k64 chunk from stage st
__device__ __forceinline__ void compute_chunk(GS* gs, int st, int wm, int wn, int lid,
                                              float acc[4][4][4]) {
    const int r_ = lid & 7, mat = lid >> 3;
    uint32_t pA = smem_u32(gs->A[st]);
    uint32_t pB = smem_u32(gs->B[st]);
#pragma unroll
    for (int s = 0; s < 4; s++) {               // 4 k16 steps
        uint32_t bf[4][2];
#pragma unroll
        for (int np = 0; np < 2; np++) {
            int row = wn * 32 + np * 16 + ((mat >> 1) << 3) + r_;
            int seg = (s << 1) | (mat & 1);
            uint32_t t[4];
            ldsm4(t, pB + sw_off(row, seg));
            bf[np * 2][0]     = t[0]; bf[np * 2][1]     = t[1];
            bf[np * 2 + 1][0] = t[2]; bf[np * 2 + 1][1] = t[3];
        }
#pragma unroll
        for (int mi = 0; mi < 4; mi++) {
            int row = wm * 64 + mi * 16 + ((mat & 1) << 3) + r_;
            int seg = (s << 1) | (mat >> 1);
            uint32_t af[4];
            ldsm4(af, pA + sw_off(row, seg));
#pragma unroll
            for (int ni = 0; ni < 4; ni++)
                mma16816(acc[mi][ni], af, bf[ni]);
        }
    }
}

// fill one stage: A gathered by tok list, B linear
__device__ __forceinline__ void fill_stage(GS* gs, int st, int tid,
                                           const uint16_t* __restrict__ A,
                                           const uint16_t* __restrict__ B,
                                           int k0, int lda, int ldb, bool gatherA, int mrem) {
    uint32_t pA = smem_u32(gs->A[st]);
    uint32_t pB = smem_u32(gs->B[st]);
#pragma unroll
    for (int i = 0; i < 4; i++) {
        int id  = tid + i * 256;   // 0..1023
        int row = id >> 3, seg = id & 7;
        uint32_t d = sw_off(row, seg);
        int vs; size_t grow;
        if (gatherA) {
            int tok = gs->toks[row];
            vs = (tok >= 0) ? 16 : 0;
            grow = (tok >= 0) ? (size_t)tok : 0;
        } else {
            vs = (row < mrem) ? 16 : 0;
            grow = (row < mrem) ? (size_t)row : 0;
        }
        cpa16(pA + d, A + grow * lda + k0 + seg * 8, vs);
        cpa16(pB + d, B + (size_t)row * ldb + k0 + seg * 8, 16);
    }
}

// ---------------- 4) GEMM1: H = relu(gather(x) @ W1 + b1) ----------------
__global__ __launch_bounds__(256, 2)
void gemm1_mma(const float* __restrict__ b1) {
    extern __shared__ __align__(16) char smraw[];
    GS* gs = (GS*)smraw;
    const int e   = blockIdx.z;
    const int cnt = g_agg.cursor[e];
    const int m0  = blockIdx.x * BM;
    if (m0 >= cnt) return;
    const int n0   = blockIdx.y * BN;
    const int off  = e * T_TOK;
    const int mrem = cnt - m0;
    const int tid  = threadIdx.x;
    const int wid  = tid >> 5, lid = tid & 31;
    const int wm = wid >> 2, wn = wid & 3;
    const int g = lid >> 2, q = lid & 3;

    if (tid < BM) {
        gs->toks[tid] = (tid < mrem) ? g_tok[off + m0 + tid] : -1;
        gs->bias[tid] = b1[(size_t)e * H_DIM + n0 + tid];
    }
    __syncthreads();

    float acc[4][4][4];
#pragma unroll
    for (int a = 0; a < 4; a++)
#pragma unroll
        for (int b = 0; b < 4; b++)
#pragma unroll
            for (int c = 0; c < 4; c++) acc[a][b][c] = 0.f;

    const uint16_t* Bp = g_W1f + ((size_t)e * H_DIM + n0) * D_DIM;

    const int NC = D_DIM / BK;   // 8
    fill_stage(gs, 0, tid, g_Xf, Bp, 0, D_DIM, D_DIM, true, mrem);
    CP_COMMIT();
    for (int c = 0; c < NC; c++) {
        int st = c & 1;
        if (c + 1 < NC) {
            fill_stage(gs, st ^ 1, tid, g_Xf, Bp, (c + 1) * BK, D_DIM, D_DIM, true, mrem);
            CP_COMMIT();
            CP_WAIT(1);
        } else {
            CP_WAIT(0);
        }
        __syncthreads();
        compute_chunk(gs, st, wm, wn, lid, acc);
        __syncthreads();
    }

    // epilogue: bias + relu -> fp16 H
#pragma unroll
    for (int mi = 0; mi < 4; mi++) {
#pragma unroll
        for (int h = 0; h < 2; h++) {
            int mrow = wm * 64 + mi * 16 + g + h * 8;
            if (mrow < mrem) {
                size_t rb = (size_t)(off + m0 + mrow) * H_DIM + n0;
#pragma unroll
                for (int ni = 0; ni < 4; ni++) {
                    int n = wn * 32 + ni * 8 + q * 2;
                    float v0 = fmaxf(acc[mi][ni][h * 2 + 0] + gs->bias[n], 0.f);
                    float v1 = fmaxf(acc[mi][ni][h * 2 + 1] + gs->bias[n + 1], 0.f);
                    *(uint32_t*)(g_Hf + rb + n) = packh2(v0, v1);
                }
            }
        }
    }
}

// ---------------- 5) GEMM2: out += gate * (H @ W2 + b2) ----------------
__global__ __launch_bounds__(256, 2)
void gemm2_mma(const float* __restrict__ b2, float* __restrict__ out) {
    extern __shared__ __align__(16) char smraw[];
    GS* gs = (GS*)smraw;
    const int e   = blockIdx.z;
    const int cnt = g_agg.cursor[e];
    const int m0  = blockIdx.x * BM;
    if (m0 >= cnt) return;
    const int n0   = blockIdx.y * BN;
    const int off  = e * T_TOK;
    const int mrem = cnt - m0;
    const int tid  = threadIdx.x;
    const int wid  = tid >> 5, lid = tid & 31;
    const int wm = wid >> 2, wn = wid & 3;
    const int g = lid >> 2, q = lid & 3;

    if (tid < BM) {
        int valid = tid < mrem;
        int s = off + m0 + tid;
        gs->toks[tid]  = valid ? g_tok[s] : -1;
        gs->gates[tid] = valid ? g_gate[s] : 0.f;
        gs->bias[tid]  = b2[(size_t)e * D_DIM + n0 + tid];
    }
    __syncthreads();

    float acc[4][4][4];
#pragma unroll
    for (int a = 0; a < 4; a++)
#pragma unroll
        for (int b = 0; b < 4; b++)
#pragma unroll
            for (int c = 0; c < 4; c++) acc[a][b][c] = 0.f;

    const uint16_t* Ap = g_Hf + (size_t)(off + m0) * H_DIM;
    const uint16_t* Bp = g_W2f + ((size_t)e * D_DIM + n0) * H_DIM;

    const int NC = H_DIM / BK;   // 16
    fill_stage(gs, 0, tid, Ap, Bp, 0, H_DIM, H_DIM, false, mrem);
    CP_COMMIT();
    for (int c = 0; c < NC; c++) {
        int st = c & 1;
        if (c + 1 < NC) {
            fill_stage(gs, st ^ 1, tid, Ap, Bp, (c + 1) * BK, H_DIM, H_DIM, false, mrem);
            CP_COMMIT();
            CP_WAIT(1);
        } else {
            CP_WAIT(0);
        }
        __syncthreads();
        compute_chunk(gs, st, wm, wn, lid, acc);
        __syncthreads();
    }

    // epilogue: (acc + bias) * gate -> float2 vector atomicAdd combine
#pragma unroll
    for (int mi = 0; mi < 4; mi++) {
#pragma unroll
        for (int h = 0; h < 2; h++) {
            int mrow = wm * 64 + mi * 16 + g + h * 8;
            if (mrow < mrem) {
                int tok  = gs->toks[mrow];
                float gt = gs->gates[mrow];
                float* dst = out + (size_t)tok * D_DIM + n0;
#pragma unroll
                for (int ni = 0; ni < 4; ni++) {
                    int n = wn * 32 + ni * 8 + q * 2;
                    float2 v = make_float2((acc[mi][ni][h * 2 + 0] + gs->bias[n]) * gt,
                                           (acc[mi][ni][h * 2 + 1] + gs->bias[n + 1]) * gt);
                    atomicAdd(reinterpret_cast<float2*>(dst + n), v);
                }
            }
        }
    }
}

// ---------------- launch ----------------
extern "C" void kernel_launch(void* const* d_in, const int* in_sizes, int n_in,
                              void* d_out, int out_size) {
    const float* x  = (const float*)d_in[0];
    const float* Wg = (const float*)d_in[1];
    const float* W1 = (const float*)d_in[2];
    const float* b1 = (const float*)d_in[3];
    const float* W2 = (const float*)d_in[4];
    const float* b2 = (const float*)d_in[5];
    float* out = (float*)d_out;

    // one-time setup on the first (uncaptured correctness) call
    static cudaStream_t s2 = nullptr;
    static cudaEvent_t evFork = nullptr, evJoin = nullptr;
    static void* aggPtr = nullptr;
    static bool init_done = false;
    if (!init_done) {
        cudaFuncSetAttribute(gemm1_mma, cudaFuncAttributeMaxDynamicSharedMemorySize, (int)GS_BYTES);
        cudaFuncSetAttribute(gemm2_mma, cudaFuncAttributeMaxDynamicSharedMemorySize, (int)GS_BYTES);
        cudaStreamCreateWithFlags(&s2, cudaStreamNonBlocking);
        cudaEventCreateWithFlags(&evFork, cudaEventDisableTiming);
        cudaEventCreateWithFlags(&evJoin, cudaEventDisableTiming);
        cudaGetSymbolAddress(&aggPtr, g_agg);
        init_done = true;
    }

    // fork: weight conversion (depends only on W1/W2) runs on s2
    cudaEventRecord(evFork, 0);
    cudaStreamWaitEvent(s2, evFork, 0);
    conv_w_kernel<<<dim3(32, 32, 2 * E_NUM), dim3(32, 8), 0, s2>>>(W1, W2);
    cudaEventRecord(evJoin, s2);

    // main stream: gating path (scatter fused into gate)
    cudaMemsetAsync(aggPtr, 0, sizeof(Agg));
    cudaMemsetAsync(out, 0, (size_t)T_TOK * D_DIM * sizeof(float));
    gate_kernel<<<T_TOK / 128, 128>>>(x, Wg);
    setup_kernel<<<1, 32>>>(out);

    // join before GEMMs
    cudaStreamWaitEvent(0, evJoin, 0);

    dim3 g1(T_TOK / BM, H_DIM / BN, E_NUM);   // (64, 8, 8), empty tiles exit
    gemm1_mma<<<g1, 256, GS_BYTES>>>(b1);

    dim3 g2(T_TOK / BM, D_DIM / BN, E_NUM);   // (64, 4, 8)
    gemm2_mma<<<g2, 256, GS_BYTES>>>(b2, out);
}

// round 16
// speedup vs baseline: 1.5998x; 1.0007x over previous
#include <cuda_runtime.h>
#include <cuda_bf16.h>
#include <cuda_fp16.h>
#include <cstdint>
#include <math.h>

// Problem constants (fixed shapes)
#define T_TOK 8192
#define D_DIM 512
#define H_DIM 1024
#define E_NUM 8
#define K_TOP 2
#define PAIRS (T_TOK * K_TOP)   // 16384

// GEMM tile config
#define BM 128
#define BN 128
#define BK 64
#define TILE_U16 (BM * BK)      // 8192 fp16 per tile (16KB)

// ---------------- device scratch (no allocations allowed) ----------------
__device__ uint16_t g_Xf[(size_t)T_TOK * D_DIM];                  // x as fp16 bits
__device__ uint16_t g_Hf[(size_t)E_NUM * T_TOK * H_DIM];          // activations fp16 (per-expert regions)
__device__ uint16_t g_W1f[(size_t)E_NUM * H_DIM * D_DIM];         // W1^T [E][H][D] fp16
__device__ uint16_t g_W2f[(size_t)E_NUM * D_DIM * H_DIM];         // W2^T [E][D][H] fp16

// aggregation block: zeroed once per launch by a single memset
struct Agg {
    float imp[E_NUM];
    int   cursor[E_NUM];     // final value == per-expert count
};
__device__ Agg g_agg;
__device__ int   g_tok[(size_t)E_NUM * T_TOK];    // fixed-capacity per-expert lists
__device__ float g_gate[(size_t)E_NUM * T_TOK];

// ---------------- helpers ----------------
__device__ __forceinline__ uint32_t smem_u32(const void* p) {
    uint32_t a;
    asm("{ .reg .u64 t; cvta.to.shared.u64 t, %1; cvt.u32.u64 %0, t; }" : "=r"(a) : "l"(p));
    return a;
}
__device__ __forceinline__ uint32_t packh2(float a, float b) {
    __half2 h = __floats2half2_rn(a, b);
    return *(uint32_t*)&h;
}

// mma.sync m16n8k16 fp16 (row.col), fp32 accum
__device__ __forceinline__ void mma16816(float* c, const uint32_t* a, const uint32_t* b) {
    asm volatile(
        "mma.sync.aligned.m16n8k16.row.col.f32.f16.f16.f32 "
        "{%0,%1,%2,%3}, {%4,%5,%6,%7}, {%8,%9}, {%0,%1,%2,%3};\n"
        : "+f"(c[0]), "+f"(c[1]), "+f"(c[2]), "+f"(c[3])
        : "r"(a[0]), "r"(a[1]), "r"(a[2]), "r"(a[3]), "r"(b[0]), "r"(b[1]));
}
__device__ __forceinline__ void ldsm4(uint32_t* r, uint32_t a) {
    asm volatile("ldmatrix.sync.aligned.m8n8.x4.shared.b16 {%0,%1,%2,%3}, [%4];"
        : "=r"(r[0]), "=r"(r[1]), "=r"(r[2]), "=r"(r[3]) : "r"(a));
}
__device__ __forceinline__ void cpa16(uint32_t dst, const void* src, int srcsz) {
    asm volatile("cp.async.cg.shared.global [%0], [%1], 16, %2;"
        :: "r"(dst), "l"(src), "r"(srcsz) : "memory");
}
#define CP_COMMIT() asm volatile("cp.async.commit_group;" ::: "memory")
#define CP_WAIT(n)  asm volatile("cp.async.wait_group %0;" :: "n"(n) : "memory")

// smem tile byte offset: 128B rows (64 fp16), seg = 16B segment (0..7), XOR swizzle
__device__ __forceinline__ uint32_t sw_off(int row, int seg) {
    return (uint32_t)(row * 128 + ((seg ^ (row & 7)) << 4));
}

// ---------------- 1) gating: logits, top-2, softmax; emits x fp16;
//                    fused scatter into fixed-capacity expert lists ----------
__global__ void gate_kernel(const float* __restrict__ x,
                            const float* __restrict__ Wg) {
    __shared__ float xs[128][68];
    __shared__ float wgs[64][8];
    __shared__ int   s_cnt[E_NUM];
    __shared__ int   s_base[E_NUM];
    __shared__ float s_imp[E_NUM];
    const int tid = threadIdx.x;
    const int t0  = blockIdx.x * 128;
    if (tid < E_NUM) { s_cnt[tid] = 0; s_imp[tid] = 0.f; }
    float acc[E_NUM];
#pragma unroll
    for (int e = 0; e < E_NUM; e++) acc[e] = 0.f;

    for (int k0 = 0; k0 < D_DIM; k0 += 64) {
#pragma unroll
        for (int i = 0; i < 4; i++) {
            int idx = tid + i * 128;
            wgs[idx >> 3][idx & 7] = Wg[(k0 + (idx >> 3)) * E_NUM + (idx & 7)];
        }
#pragma unroll
        for (int i = 0; i < 16; i++) {
            int f4  = i * 128 + tid;
            int row = f4 >> 4;
            int c4  = f4 & 15;
            float4 v = *(const float4*)(x + (size_t)(t0 + row) * D_DIM + k0 + c4 * 4);
            *(float4*)&xs[row][c4 * 4] = v;
            size_t o = (size_t)(t0 + row) * D_DIM + k0 + c4 * 4;
            *(uint2*)(g_Xf + o) = make_uint2(packh2(v.x, v.y), packh2(v.z, v.w));
        }
        __syncthreads();
#pragma unroll 8
        for (int k = 0; k < 64; k++) {
            float xv = xs[tid][k];
#pragma unroll
            for (int e = 0; e < E_NUM; e++) acc[e] = fmaf(xv, wgs[k][e], acc[e]);
        }
        __syncthreads();
    }
    int e0 = 0; float v0 = acc[0];
#pragma unroll
    for (int e = 1; e < E_NUM; e++) if (acc[e] > v0) { v0 = acc[e]; e0 = e; }
    int e1 = -1; float v1 = -INFINITY;
#pragma unroll
    for (int e = 0; e < E_NUM; e++) if (e != e0 && acc[e] > v1) { v1 = acc[e]; e1 = e; }
    float p1 = __expf(v1 - v0);
    float inv = 1.f / (1.f + p1);
    float gv0 = inv, gv1 = p1 * inv;
    int t = t0 + tid;

    // fused scatter: block-local ranks, one cursor atomic per expert per block
    int r0 = atomicAdd(&s_cnt[e0], 1);
    int r1 = atomicAdd(&s_cnt[e1], 1);
    atomicAdd(&s_imp[e0], gv0);
    atomicAdd(&s_imp[e1], gv1);
    __syncthreads();
    if (tid < E_NUM) {
        s_base[tid] = atomicAdd(&g_agg.cursor[tid], s_cnt[tid]);
        atomicAdd(&g_agg.imp[tid], s_imp[tid]);
    }
    __syncthreads();
    {
        int s = e0 * T_TOK + s_base[e0] + r0;
        g_tok[s] = t; g_gate[s] = gv0;
    }
    {
        int s = e1 * T_TOK + s_base[e1] + r1;
        g_tok[s] = t; g_gate[s] = gv1;
    }
}

// ---------------- 2) setup: losses from pre-reduced sums ----------
__global__ void setup_kernel(float* __restrict__ out) {
    if (threadIdx.x != 0) return;
    const float eps = 1e-10f;
    float mi = 0.f, ml = 0.f;
    int cnts[E_NUM]; float imps[E_NUM];
#pragma unroll
    for (int e = 0; e < E_NUM; e++) {
        cnts[e] = g_agg.cursor[e];
        imps[e] = g_agg.imp[e];
        mi += imps[e];
        ml += (float)cnts[e];
    }
    mi /= E_NUM; ml /= E_NUM;
    float vi = 0.f, vl = 0.f;
#pragma unroll
    for (int e = 0; e < E_NUM; e++) {
        float di = imps[e] - mi; vi += di * di;
        float dl = (float)cnts[e] - ml; vl += dl * dl;
    }
    vi /= (E_NUM - 1); vl /= (E_NUM - 1);
    out[(size_t)T_TOK * D_DIM]     = vi / (mi * mi + eps);
    out[(size_t)T_TOK * D_DIM + 1] = vl / (ml * ml + eps);
}

// ------------- weight transpose + fp16 convert (fused W1+W2) -------------
template <int R, int C>
__device__ __forceinline__ void transpose_half(const float* __restrict__ s,
                                               uint16_t* __restrict__ d) {
    __shared__ float tile[32][33];
    int c0 = blockIdx.x * 32, r0 = blockIdx.y * 32;
#pragma unroll
    for (int i = 0; i < 32; i += 8)
        tile[threadIdx.y + i][threadIdx.x] = s[(size_t)(r0 + threadIdx.y + i) * C + c0 + threadIdx.x];
    __syncthreads();
#pragma unroll
    for (int i = 0; i < 32; i += 8) {
        float v = tile[threadIdx.x][threadIdx.y + i];
        __half h = __float2half_rn(v);
        d[(size_t)(c0 + threadIdx.y + i) * R + r0 + threadIdx.x] = *(uint16_t*)&h;
    }
}
// grid: (32, 32, 2*E); per-branch bounds guards.
__global__ void conv_w_kernel(const float* __restrict__ W1,
                              const float* __restrict__ W2) {
    int z = blockIdx.z;
    if (z < E_NUM) {
        if (blockIdx.x >= H_DIM / 32 || blockIdx.y >= D_DIM / 32) return;
        size_t eo = (size_t)z * D_DIM * H_DIM;
        transpose_half<D_DIM, H_DIM>(W1 + eo, g_W1f + eo);
    } else {
        if (blockIdx.x >= D_DIM / 32 || blockIdx.y >= H_DIM / 32) return;
        size_t eo = (size_t)(z - E_NUM) * H_DIM * D_DIM;
        transpose_half<H_DIM, D_DIM>(W2 + eo, g_W2f + eo);
    }
}

// ---------------- shared GEMM smem ----------------
struct GS {
    uint16_t A[2][TILE_U16];
    uint16_t B[2][TILE_U16];
    int   toks[BM];
    float gates[BM];
    float bias[BN];
};
#define GS_BYTES sizeof(GS)

// compute one k64 chunk from stage st
__device__ __forceinline__ void compute_chunk(GS* gs, int st, int wm, int wn, int lid,
                                              float acc[4][4][4]) {
    const int r_ = lid & 7, mat = lid >> 3;
    uint32_t pA = smem_u32(gs->A[st]);
    uint32_t pB = smem_u32(gs->B[st]);
#pragma unroll
    for (int s = 0; s < 4; s++) {               // 4 k16 steps
        uint32_t bf[4][2];
#pragma unroll
        for (int np = 0; np < 2; np++) {
            int row = wn * 32 + np * 16 + ((mat >> 1) << 3) + r_;
            int seg = (s << 1) | (mat & 1);
            uint32_t t[4];
            ldsm4(t, pB + sw_off(row, seg));
            bf[np * 2][0]     = t[0]; bf[np * 2][1]     = t[1];
            bf[np * 2 + 1][0] = t[2]; bf[np * 2 + 1][1] = t[3];
        }
#pragma unroll
        for (int mi = 0; mi < 4; mi++) {
            int row = wm * 64 + mi * 16 + ((mat & 1) << 3) + r_;
            int seg = (s << 1) | (mat >> 1);
            uint32_t af[4];
            ldsm4(af, pA + sw_off(row, seg));
#pragma unroll
            for (int ni = 0; ni < 4; ni++)
                mma16816(acc[mi][ni], af, bf[ni]);
        }
    }
}

// fill one stage: A gathered by tok list, B linear
__device__ __forceinline__ void fill_stage(GS* gs, int st, int tid,
                                           const uint16_t* __restrict__ A,
                                           const uint16_t* __restrict__ B,
                                           int k0, int lda, int ldb, bool gatherA, int mrem) {
    uint32_t pA = smem_u32(gs->A[st]);
    uint32_t pB = smem_u32(gs->B[st]);
#pragma unroll
    for (int i = 0; i < 4; i++) {
        int id  = tid + i * 256;   // 0..1023
        int row = id >> 3, seg = id & 7;
        uint32_t d = sw_off(row, seg);
        int vs; size_t grow;
        if (gatherA) {
            int tok = gs->toks[row];
            vs = (tok >= 0) ? 16 : 0;
            grow = (tok >= 0) ? (size_t)tok : 0;
        } else {
            vs = (row < mrem) ? 16 : 0;
            grow = (row < mrem) ? (size_t)row : 0;
        }
        cpa16(pA + d, A + grow * lda + k0 + seg * 8, vs);
        cpa16(pB + d, B + (size_t)row * ldb + k0 + seg * 8, 16);
    }
}

// single-barrier double-buffered mainloop (wait -> barrier -> fill -> compute):
//  CP_WAIT(0): this thread's fill of chunk c has landed (it had all of
//              compute c-1 to fly).
//  __syncthreads(): publishes every thread's landed data (visibility) AND
//              guarantees all threads finished compute c-1 before stage st^1
//              is overwritten below (anti-dependence).
//  fill chunk c+1 into st^1, commit; overlaps compute of chunk c.
#define GEMM_MAINLOOP(NC, Ap, Bp, lda, ldb, gatherA)                              \
    fill_stage(gs, 0, tid, Ap, Bp, 0, lda, ldb, gatherA, mrem); CP_COMMIT();      \
    for (int c = 0; c < (NC); c++) {                                              \
        int st = c & 1;                                                           \
        CP_WAIT(0);                                                               \
        __syncthreads();                                                          \
        if (c + 1 < (NC)) {                                                       \
            fill_stage(gs, st ^ 1, tid, Ap, Bp, (c + 1) * BK, lda, ldb,           \
                       gatherA, mrem);                                            \
            CP_COMMIT();                                                          \
        }                                                                         \
        compute_chunk(gs, st, wm, wn, lid, acc);                                  \
    }

// ---------------- 4) GEMM1: H = relu(gather(x) @ W1 + b1) ----------------
__global__ __launch_bounds__(256, 2)
void gemm1_mma(const float* __restrict__ b1) {
    extern __shared__ __align__(16) char smraw[];
    GS* gs = (GS*)smraw;
    const int e   = blockIdx.z;
    const int cnt = g_agg.cursor[e];
    const int m0  = blockIdx.x * BM;
    if (m0 >= cnt) return;
    const int n0   = blockIdx.y * BN;
    const int off  = e * T_TOK;
    const int mrem = cnt - m0;
    const int tid  = threadIdx.x;
    const int wid  = tid >> 5, lid = tid & 31;
    const int wm = wid >> 2, wn = wid & 3;
    const int g = lid >> 2, q = lid & 3;

    if (tid < BM) {
        gs->toks[tid] = (tid < mrem) ? g_tok[off + m0 + tid] : -1;
        gs->bias[tid] = b1[(size_t)e * H_DIM + n0 + tid];
    }
    __syncthreads();

    float acc[4][4][4];
#pragma unroll
    for (int a = 0; a < 4; a++)
#pragma unroll
        for (int b = 0; b < 4; b++)
#pragma unroll
            for (int c = 0; c < 4; c++) acc[a][b][c] = 0.f;

    const uint16_t* Bp = g_W1f + ((size_t)e * H_DIM + n0) * D_DIM;

    GEMM_MAINLOOP(D_DIM / BK, g_Xf, Bp, D_DIM, D_DIM, true);

    // epilogue: bias + relu -> fp16 H
#pragma unroll
    for (int mi = 0; mi < 4; mi++) {
#pragma unroll
        for (int h = 0; h < 2; h++) {
            int mrow = wm * 64 + mi * 16 + g + h * 8;
            if (mrow < mrem) {
                size_t rb = (size_t)(off + m0 + mrow) * H_DIM + n0;
#pragma unroll
                for (int ni = 0; ni < 4; ni++) {
                    int n = wn * 32 + ni * 8 + q * 2;
                    float v0 = fmaxf(acc[mi][ni][h * 2 + 0] + gs->bias[n], 0.f);
                    float v1 = fmaxf(acc[mi][ni][h * 2 + 1] + gs->bias[n + 1], 0.f);
                    *(uint32_t*)(g_Hf + rb + n) = packh2(v0, v1);
                }
            }
        }
    }
}

// ---------------- 5) GEMM2: out += gate * (H @ W2 + b2) ----------------
__global__ __launch_bounds__(256, 2)
void gemm2_mma(const float* __restrict__ b2, float* __restrict__ out) {
    extern __shared__ __align__(16) char smraw[];
    GS* gs = (GS*)smraw;
    const int e   = blockIdx.z;
    const int cnt = g_agg.cursor[e];
    const int m0  = blockIdx.x * BM;
    if (m0 >= cnt) return;
    const int n0   = blockIdx.y * BN;
    const int off  = e * T_TOK;
    const int mrem = cnt - m0;
    const int tid  = threadIdx.x;
    const int wid  = tid >> 5, lid = tid & 31;
    const int wm = wid >> 2, wn = wid & 3;
    const int g = lid >> 2, q = lid & 3;

    if (tid < BM) {
        int valid = tid < mrem;
        int s = off + m0 + tid;
        gs->toks[tid]  = valid ? g_tok[s] : -1;
        gs->gates[tid] = valid ? g_gate[s] : 0.f;
        gs->bias[tid]  = b2[(size_t)e * D_DIM + n0 + tid];
    }
    __syncthreads();

    float acc[4][4][4];
#pragma unroll
    for (int a = 0; a < 4; a++)
#pragma unroll
        for (int b = 0; b < 4; b++)
#pragma unroll
            for (int c = 0; c < 4; c++) acc[a][b][c] = 0.f;

    const uint16_t* Ap = g_Hf + (size_t)(off + m0) * H_DIM;
    const uint16_t* Bp = g_W2f + ((size_t)e * D_DIM + n0) * H_DIM;

    GEMM_MAINLOOP(H_DIM / BK, Ap, Bp, H_DIM, H_DIM, false);

    // epilogue: (acc + bias) * gate -> float2 vector atomicAdd combine
#pragma unroll
    for (int mi = 0; mi < 4; mi++) {
#pragma unroll
        for (int h = 0; h < 2; h++) {
            int mrow = wm * 64 + mi * 16 + g + h * 8;
            if (mrow < mrem) {
                int tok  = gs->toks[mrow];
                float gt = gs->gates[mrow];
                float* dst = out + (size_t)tok * D_DIM + n0;
#pragma unroll
                for (int ni = 0; ni < 4; ni++) {
                    int n = wn * 32 + ni * 8 + q * 2;
                    float2 v = make_float2((acc[mi][ni][h * 2 + 0] + gs->bias[n]) * gt,
                                           (acc[mi][ni][h * 2 + 1] + gs->bias[n + 1]) * gt);
                    atomicAdd(reinterpret_cast<float2*>(dst + n), v);
                }
            }
        }
    }
}

// ---------------- launch ----------------
extern "C" void kernel_launch(void* const* d_in, const int* in_sizes, int n_in,
                              void* d_out, int out_size) {
    const float* x  = (const float*)d_in[0];
    const float* Wg = (const float*)d_in[1];
    const float* W1 = (const float*)d_in[2];
    const float* b1 = (const float*)d_in[3];
    const float* W2 = (const float*)d_in[4];
    const float* b2 = (const float*)d_in[5];
    float* out = (float*)d_out;

    // one-time setup on the first (uncaptured correctness) call
    static cudaStream_t s2 = nullptr;
    static cudaEvent_t evFork = nullptr, evJoin = nullptr;
    static void* aggPtr = nullptr;
    static bool init_done = false;
    if (!init_done) {
        cudaFuncSetAttribute(gemm1_mma, cudaFuncAttributeMaxDynamicSharedMemorySize, (int)GS_BYTES);
        cudaFuncSetAttribute(gemm2_mma, cudaFuncAttributeMaxDynamicSharedMemorySize, (int)GS_BYTES);
        cudaStreamCreateWithFlags(&s2, cudaStreamNonBlocking);
        cudaEventCreateWithFlags(&evFork, cudaEventDisableTiming);
        cudaEventCreateWithFlags(&evJoin, cudaEventDisableTiming);
        cudaGetSymbolAddress(&aggPtr, g_agg);
        init_done = true;
    }

    // fork: weight conversion (depends only on W1/W2) runs on s2
    cudaEventRecord(evFork, 0);
    cudaStreamWaitEvent(s2, evFork, 0);
    conv_w_kernel<<<dim3(32, 32, 2 * E_NUM), dim3(32, 8), 0, s2>>>(W1, W2);
    cudaEventRecord(evJoin, s2);

    // main stream: gating path (scatter fused into gate)
    cudaMemsetAsync(aggPtr, 0, sizeof(Agg));
    cudaMemsetAsync(out, 0, (size_t)T_TOK * D_DIM * sizeof(float));
    gate_kernel<<<T_TOK / 128, 128>>>(x, Wg);
    setup_kernel<<<1, 32>>>(out);

    // join before GEMMs
    cudaStreamWaitEvent(0, evJoin, 0);

    dim3 g1(T_TOK / BM, H_DIM / BN, E_NUM);   // (64, 8, 8), empty tiles exit
    gemm1_mma<<<g1, 256, GS_BYTES>>>(b1);

    dim3 g2(T_TOK / BM, D_DIM / BN, E_NUM);   // (64, 4, 8)
    gemm2_mma<<<g2, 256, GS_BYTES>>>(b2, out);
}